// round 8
// baseline (speedup 1.0000x reference)
#include <cuda_runtime.h>
#include <cuda_fp16.h>
#include <cstdint>

#define Cdim 1024
#define Hn   16
#define NB   8
#define Lseq 4096
#define Mrows (NB * Lseq)      // 32768
#define ATT_SCALE 0.125f

// ---------------------------------------------------------------------------
// Scratch
// ---------------------------------------------------------------------------
__device__ float g_logits[(size_t)Mrows * Hn];
__device__ float g_wbuf[(size_t)NB * Hn * Lseq];
__device__ float g_pq[NB * Cdim];
__device__ float g_pk[NB * Cdim];

__device__ __half g_xq16[(size_t)Mrows * Cdim];
__device__ __half g_xkv16[(size_t)Mrows * Cdim];
__device__ __half g_Q16[(size_t)Mrows * Cdim];
__device__ __half g_K16[(size_t)Mrows * Cdim];
__device__ __half g_V16[(size_t)Mrows * Cdim];
__device__ __half g_T16[(size_t)Mrows * Cdim];
__device__ __half g_WT[5][(size_t)Cdim * Cdim];

// ---------------------------------------------------------------------------
// PTX helpers
// ---------------------------------------------------------------------------
__device__ __forceinline__ uint32_t smem_u32(const void* p) {
    uint32_t a;
    asm("{ .reg .u64 t; cvta.to.shared.u64 t, %1; cvt.u32.u64 %0, t; }" : "=r"(a) : "l"(p));
    return a;
}
__device__ __forceinline__ void cpa16(uint32_t dst, const void* src) {
    asm volatile("cp.async.cg.shared.global [%0], [%1], 16;" :: "r"(dst), "l"(src) : "memory");
}
__device__ __forceinline__ void cpa_commit() {
    asm volatile("cp.async.commit_group;" ::: "memory");
}
__device__ __forceinline__ void cpa_wait1() {
    asm volatile("cp.async.wait_group 1;" ::: "memory");
}
__device__ __forceinline__ void ldm_x4(uint32_t* r, uint32_t addr) {
    asm volatile("ldmatrix.sync.aligned.m8n8.x4.shared.b16 {%0,%1,%2,%3}, [%4];"
                 : "=r"(r[0]), "=r"(r[1]), "=r"(r[2]), "=r"(r[3]) : "r"(addr));
}
__device__ __forceinline__ void mma_fp16(float* c, const uint32_t* a, const uint32_t* b) {
    asm volatile(
        "mma.sync.aligned.m16n8k16.row.col.f32.f16.f16.f32 "
        "{%0,%1,%2,%3}, {%4,%5,%6,%7}, {%8,%9}, {%0,%1,%2,%3};"
        : "+f"(c[0]), "+f"(c[1]), "+f"(c[2]), "+f"(c[3])
        : "r"(a[0]), "r"(a[1]), "r"(a[2]), "r"(a[3]), "r"(b[0]), "r"(b[1]));
}

// ---------------------------------------------------------------------------
// HMMA GEMM: out[M,1024] = A[M,1024] @ W[1024,1024] (+epilogues)
// A fp16 row-major; W fp16 K-major. Block 128x128, BK=64, 3 stages, 2 CTA/SM.
// ---------------------------------------------------------------------------
#define ROWB   144                 // 64 fp16 = 128B data + 16B pad
#define TILEB  (128 * ROWB)        // 18432
#define STAGEB (2 * TILEB)         // A, B -> 36864
#define STAGES 3
#define SMEMB  (STAGES * STAGEB)   // 110592

__device__ __forceinline__ void issue_stage(
    uint32_t sb, int s, int chunk, int tid,
    const __half* Aw, const __half* Bw, int grow0, int ncol0)
{
    uint32_t stb = sb + (uint32_t)s * STAGEB;
    int k0 = chunk * 64;
#pragma unroll
    for (int j = 0; j < 8; j++) {
        int id = tid + j * 256;            // 0..2047
        int t4 = id >> 10;                 // operand tile 0..1
        int w  = id & 1023;
        int r  = w >> 3, c = w & 7;        // row, 16B chunk
        const __half* src = (t4 == 0) ? Aw : Bw;
        int rb = (t4 == 0) ? grow0 : ncol0;
        const void* g = src + ((size_t)(rb + r) * Cdim + k0 + c * 8);
        cpa16(stb + (uint32_t)t4 * TILEB + (uint32_t)(r * ROWB + c * 16), g);
    }
}

__global__ void __launch_bounds__(256, 2) mma_gemm(
    const __half* __restrict__ Aw, const __half* __restrict__ Bw,
    const float* __restrict__ bias, const float* __restrict__ colscale,
    const __half* __restrict__ addmat,
    float* __restrict__ outf, __half* __restrict__ out16)
{
    extern __shared__ char smem[];
    uint32_t sb = smem_u32(smem);
    int tid = threadIdx.x;
    int lane = tid & 31, wid = tid >> 5;
    int wm = wid & 1, wc = wid >> 1;           // warp 64x32 tile: 2 x 4 grid
    int bM = blockIdx.y * 128, bN = blockIdx.x * 128;

    float acc[4][4][4];
#pragma unroll
    for (int i = 0; i < 4; i++)
#pragma unroll
        for (int j = 0; j < 4; j++)
#pragma unroll
            for (int q = 0; q < 4; q++) acc[i][j][q] = 0.f;

    int grp = lane >> 3, l7 = lane & 7;
    uint32_t a_off = (uint32_t)((l7 + ((grp & 1) << 3)) * ROWB + ((grp >> 1) << 4));
    uint32_t b_off = (uint32_t)((l7 + ((grp >> 1) << 3)) * ROWB + ((grp & 1) << 4));

    // prologue: 2 chunks
#pragma unroll
    for (int s = 0; s < 2; s++) {
        issue_stage(sb, s, s, tid, Aw, Bw, bM, bN);
        cpa_commit();
    }

    for (int k = 0; k < 16; k++) {
        cpa_wait1();
        __syncthreads();
        if (k + 2 < 16)
            issue_stage(sb, (k + 2) % 3, k + 2, tid, Aw, Bw, bM, bN);
        cpa_commit();

        uint32_t st = sb + (uint32_t)(k % 3) * STAGEB;
#pragma unroll
        for (int kk = 0; kk < 4; kk++) {
            uint32_t kb = (uint32_t)(kk * 32);
            uint32_t bh[8];
#pragma unroll
            for (int h = 0; h < 2; h++) {
                uint32_t nrow = (uint32_t)((wc * 32 + h * 16) * ROWB);
                ldm_x4(bh + h * 4, st + TILEB + nrow + b_off + kb);
            }
#pragma unroll
            for (int mt = 0; mt < 4; mt++) {
                uint32_t mrow = (uint32_t)((wm * 64 + mt * 16) * ROWB);
                uint32_t ah[4];
                ldm_x4(ah, st + mrow + a_off + kb);
#pragma unroll
                for (int nt = 0; nt < 4; nt++)
                    mma_fp16(acc[mt][nt], ah, &bh[nt * 2]);
            }
        }
    }

    // ---------------- epilogue ----------------
    int nidx = bM >> 12;
#pragma unroll
    for (int mt = 0; mt < 4; mt++) {
        int m0 = bM + wm * 64 + mt * 16 + (lane >> 2);
#pragma unroll
        for (int nt = 0; nt < 4; nt++) {
            int n = bN + wc * 32 + nt * 8 + (lane & 3) * 2;
            float b0 = bias[n], b1 = bias[n + 1];
            float v0 = acc[mt][nt][0] + b0, v1 = acc[mt][nt][1] + b1;
            float v2 = acc[mt][nt][2] + b0, v3 = acc[mt][nt][3] + b1;
            if (colscale) {
                float s0 = colscale[nidx * Cdim + n];
                float s1 = colscale[nidx * Cdim + n + 1];
                v0 *= s0; v1 *= s1; v2 *= s0; v3 *= s1;
            }
            size_t o0 = (size_t)m0 * Cdim + n;
            size_t o1 = (size_t)(m0 + 8) * Cdim + n;
            if (addmat) {
                float2 a0 = __half22float2(*(const __half2*)(addmat + o0));
                float2 a1 = __half22float2(*(const __half2*)(addmat + o1));
                v0 += a0.x; v1 += a0.y; v2 += a1.x; v3 += a1.y;
            }
            if (outf) {
                *(float2*)(outf + o0) = make_float2(v0, v1);
                *(float2*)(outf + o1) = make_float2(v2, v3);
            }
            if (out16) {
                *(__half2*)(out16 + o0) =
                    __halves2half2(__float2half(v0), __float2half(v1));
                *(__half2*)(out16 + o1) =
                    __halves2half2(__float2half(v2), __float2half(v3));
            }
        }
    }
}

// ---------------------------------------------------------------------------
// fp32 -> fp16 elementwise
// ---------------------------------------------------------------------------
__global__ __launch_bounds__(256) void cvt_kernel(
    const float* __restrict__ src, __half* __restrict__ dst, int n4)
{
    int i = blockIdx.x * 256 + threadIdx.x;
    if (i >= n4) return;
    float4 x = ((const float4*)src)[i];
    __half2 a = __halves2half2(__float2half(x.x), __float2half(x.y));
    __half2 b = __halves2half2(__float2half(x.z), __float2half(x.w));
    ((__half2*)dst)[2 * i] = a;
    ((__half2*)dst)[2 * i + 1] = b;
}

// ---------------------------------------------------------------------------
// W[k][n] fp32 -> WT[n][k] fp16 (transpose-convert)
// ---------------------------------------------------------------------------
__global__ __launch_bounds__(256) void wcvt_kernel(
    const float* __restrict__ W, __half* __restrict__ T16)
{
    __shared__ float t[32][33];
    int tx = threadIdx.x & 31, ty = threadIdx.x >> 5;
    int n0 = blockIdx.x * 32, k0 = blockIdx.y * 32;
#pragma unroll
    for (int i = 0; i < 32; i += 8)
        t[ty + i][tx] = W[(size_t)(k0 + ty + i) * Cdim + n0 + tx];
    __syncthreads();
#pragma unroll
    for (int i = 0; i < 32; i += 8) {
        size_t o = (size_t)(n0 + ty + i) * Cdim + k0 + tx;
        T16[o] = __float2half(t[tx][ty + i]);
    }
}

// ---------------------------------------------------------------------------
// logits[row,h] = (sum_c A16[row,c] * (sv? sv[n,c]:1) * W16[c,h] + b16[h]) * SCALE
// ---------------------------------------------------------------------------
__global__ __launch_bounds__(256) void attn_logits_kernel(
    const __half* __restrict__ A, const float* __restrict__ W16,
    const float* __restrict__ b16, const float* __restrict__ scalevec,
    float* __restrict__ logits)
{
    int warp = threadIdx.x >> 5, lane = threadIdx.x & 31;
    int row = blockIdx.x * 8 + warp;
    int n = row >> 12;
    const __half2* arow = (const __half2*)(A + (size_t)row * Cdim);
    const float* sv = scalevec ? scalevec + (size_t)n * Cdim : nullptr;

    float acc[16];
#pragma unroll
    for (int h = 0; h < 16; h++) acc[h] = 0.f;

    for (int cc = lane; cc < Cdim / 2; cc += 32) {
        float2 a2 = __half22float2(arow[cc]);
        int c = cc * 2;
        if (sv) { a2.x *= sv[c]; a2.y *= sv[c + 1]; }
#pragma unroll
        for (int half = 0; half < 2; half++) {
            float a = half ? a2.y : a2.x;
            const float4* w4 = (const float4*)(W16 + (size_t)(c + half) * 16);
            float4 w0 = w4[0], w1 = w4[1], w2 = w4[2], w3 = w4[3];
            acc[0]  = fmaf(a, w0.x, acc[0]);  acc[1]  = fmaf(a, w0.y, acc[1]);
            acc[2]  = fmaf(a, w0.z, acc[2]);  acc[3]  = fmaf(a, w0.w, acc[3]);
            acc[4]  = fmaf(a, w1.x, acc[4]);  acc[5]  = fmaf(a, w1.y, acc[5]);
            acc[6]  = fmaf(a, w1.z, acc[6]);  acc[7]  = fmaf(a, w1.w, acc[7]);
            acc[8]  = fmaf(a, w2.x, acc[8]);  acc[9]  = fmaf(a, w2.y, acc[9]);
            acc[10] = fmaf(a, w2.z, acc[10]); acc[11] = fmaf(a, w2.w, acc[11]);
            acc[12] = fmaf(a, w3.x, acc[12]); acc[13] = fmaf(a, w3.y, acc[13]);
            acc[14] = fmaf(a, w3.z, acc[14]); acc[15] = fmaf(a, w3.w, acc[15]);
        }
    }
#pragma unroll
    for (int h = 0; h < 16; h++) {
        float v = acc[h];
#pragma unroll
        for (int o = 16; o; o >>= 1) v += __shfl_xor_sync(0xffffffffu, v, o);
        if (lane == h) logits[(size_t)row * 16 + h] = (v + b16[h]) * ATT_SCALE;
    }
}

__global__ __launch_bounds__(256) void softmax_L_kernel(
    const float* __restrict__ logits, float* __restrict__ w_out)
{
    int n = blockIdx.x / Hn, h = blockIdx.x % Hn;
    __shared__ float buf[Lseq];
    __shared__ float red[256];
    int tid = threadIdx.x;

    float m = -1e30f;
    for (int l = tid; l < Lseq; l += 256) {
        float v = logits[((size_t)n * Lseq + l) * Hn + h];
        buf[l] = v;
        m = fmaxf(m, v);
    }
    red[tid] = m; __syncthreads();
    for (int s = 128; s; s >>= 1) {
        if (tid < s) red[tid] = fmaxf(red[tid], red[tid + s]);
        __syncthreads();
    }
    m = red[0]; __syncthreads();

    float sum = 0.f;
    for (int l = tid; l < Lseq; l += 256) {
        float e = __expf(buf[l] - m);
        buf[l] = e;
        sum += e;
    }
    red[tid] = sum; __syncthreads();
    for (int s = 128; s; s >>= 1) {
        if (tid < s) red[tid] += red[tid + s];
        __syncthreads();
    }
    float inv = 1.f / red[0];

    float* wp = w_out + ((size_t)n * Hn + h) * Lseq;
    for (int l = tid; l < Lseq; l += 256) wp[l] = buf[l] * inv;
}

// ---------------------------------------------------------------------------
// pooled[n, h*64+dh] = sum_l w[n,h,l] * A16[n,l, h*64+dh]
// ---------------------------------------------------------------------------
__global__ __launch_bounds__(1024) void pool_kernel(
    const float* __restrict__ w, const __half* __restrict__ A,
    float* __restrict__ pooled)
{
    int h = blockIdx.x, n = blockIdx.y;
    int tid = threadIdx.x;
    int dh = tid & 63, g = tid >> 6;

    const float* wp = w + ((size_t)n * Hn + h) * Lseq + g * 256;
    const __half* ap = A + ((size_t)(n * Lseq + g * 256)) * Cdim + h * 64 + dh;

    float a0 = 0.f, a1 = 0.f, a2 = 0.f, a3 = 0.f;
    for (int l = 0; l < 256; l += 4) {
        a0 = fmaf(wp[l + 0], __half2float(ap[(size_t)(l + 0) * Cdim]), a0);
        a1 = fmaf(wp[l + 1], __half2float(ap[(size_t)(l + 1) * Cdim]), a1);
        a2 = fmaf(wp[l + 2], __half2float(ap[(size_t)(l + 2) * Cdim]), a2);
        a3 = fmaf(wp[l + 3], __half2float(ap[(size_t)(l + 3) * Cdim]), a3);
    }
    __shared__ float red[1024];
    red[tid] = a0 + a1 + a2 + a3;
    __syncthreads();
    if (tid < 64) {
        float s = 0.f;
#pragma unroll
        for (int gg = 0; gg < 16; gg++) s += red[dh + gg * 64];
        pooled[(size_t)n * Cdim + h * 64 + dh] = s;
    }
}

// ---------------------------------------------------------------------------
// Launch
// ---------------------------------------------------------------------------
extern "C" void kernel_launch(void* const* d_in, const int* in_sizes, int n_in,
                              void* d_out, int out_size)
{
    const float* x_q  = (const float*)d_in[0];
    const float* x_kv = (const float*)d_in[1];
    const float* Wq   = (const float*)d_in[2];
    const float* bq   = (const float*)d_in[3];
    const float* Wqa  = (const float*)d_in[4];
    const float* bqa  = (const float*)d_in[5];
    const float* Wk   = (const float*)d_in[6];
    const float* bk   = (const float*)d_in[7];
    const float* Wka  = (const float*)d_in[8];
    const float* bka  = (const float*)d_in[9];
    const float* Wv   = (const float*)d_in[10];
    const float* bv   = (const float*)d_in[11];
    const float* Wt   = (const float*)d_in[12];
    const float* bt   = (const float*)d_in[13];
    const float* Wp   = (const float*)d_in[14];
    const float* bp   = (const float*)d_in[15];
    float* out = (float*)d_out;

    float *lg, *wb, *pq, *pk;
    __half *xq16, *xkv16, *Q16, *K16, *V16, *T16, *WT;
    cudaGetSymbolAddress((void**)&lg, g_logits);
    cudaGetSymbolAddress((void**)&wb, g_wbuf);
    cudaGetSymbolAddress((void**)&pq, g_pq);
    cudaGetSymbolAddress((void**)&pk, g_pk);
    cudaGetSymbolAddress((void**)&xq16, g_xq16);
    cudaGetSymbolAddress((void**)&xkv16, g_xkv16);
    cudaGetSymbolAddress((void**)&Q16, g_Q16);
    cudaGetSymbolAddress((void**)&K16, g_K16);
    cudaGetSymbolAddress((void**)&V16, g_V16);
    cudaGetSymbolAddress((void**)&T16, g_T16);
    cudaGetSymbolAddress((void**)&WT, g_WT);

    const size_t WSZ = (size_t)Cdim * Cdim;
    __half *wq16 = WT + 0 * WSZ, *wk16 = WT + 1 * WSZ, *wv16 = WT + 2 * WSZ;
    __half *wt16 = WT + 3 * WSZ, *wp16 = WT + 4 * WSZ;

    cudaFuncSetAttribute(mma_gemm, cudaFuncAttributeMaxDynamicSharedMemorySize, SMEMB);

    int n4 = Mrows * Cdim / 4;
    dim3 wg(32, 32);
    cvt_kernel<<<(n4 + 255) / 256, 256>>>(x_q, xq16, n4);        // 0
    cvt_kernel<<<(n4 + 255) / 256, 256>>>(x_kv, xkv16, n4);      // 1
    wcvt_kernel<<<wg, 256>>>(Wq, wq16);                          // 2
    wcvt_kernel<<<wg, 256>>>(Wk, wk16);                          // 3
    wcvt_kernel<<<wg, 256>>>(Wv, wv16);                          // 4

    dim3 gg(Cdim / 128, Mrows / 128);   // 8 x 256

    // 5: Q = x_q @ Wq + bq  (fp16 only)
    mma_gemm<<<gg, 256, SMEMB>>>(xq16, wq16, bq, nullptr, nullptr, nullptr, Q16);
    wcvt_kernel<<<wg, 256>>>(Wt, wt16);
    wcvt_kernel<<<wg, 256>>>(Wp, wp16);
    // q pooling
    attn_logits_kernel<<<Mrows / 8, 256>>>(Q16, Wqa, bqa, nullptr, lg);
    softmax_L_kernel<<<NB * Hn, 256>>>(lg, wb);
    pool_kernel<<<dim3(Hn, NB), 1024>>>(wb, Q16, pq);
    // K = x_kv @ Wk + bk  (fp16 only)
    mma_gemm<<<gg, 256, SMEMB>>>(xkv16, wk16, bk, nullptr, nullptr, nullptr, K16);
    // k pooling (gated logits)
    attn_logits_kernel<<<Mrows / 8, 256>>>(K16, Wka, bka, pq, lg);
    softmax_L_kernel<<<NB * Hn, 256>>>(lg, wb);
    pool_kernel<<<dim3(Hn, NB), 1024>>>(wb, K16, pk);
    // Vs = (x_kv @ Wv + bv) * pk[n,col]  (fp16 only)
    mma_gemm<<<gg, 256, SMEMB>>>(xkv16, wv16, bv, pk, nullptr, nullptr, V16);
    // T = Vs @ Wt + bt + Q16  (fp16 only)
    mma_gemm<<<gg, 256, SMEMB>>>(V16, wt16, bt, nullptr, Q16, nullptr, T16);
    // out = T @ Wp + bp  (fp32)
    mma_gemm<<<gg, 256, SMEMB>>>(T16, wp16, bp, nullptr, nullptr, out, nullptr);
}

// round 9
// speedup vs baseline: 1.2679x; 1.2679x over previous
#include <cuda_runtime.h>
#include <cuda_fp16.h>
#include <cstdint>

#define Cdim 1024
#define Hn   16
#define NB   8
#define Lseq 4096
#define Mrows (NB * Lseq)      // 32768
#define ATT_SCALE 0.125f

// ---------------------------------------------------------------------------
// Scratch
// ---------------------------------------------------------------------------
__device__ float g_Q[(size_t)Mrows * Cdim];
__device__ float g_K[(size_t)Mrows * Cdim];
__device__ float g_logits[(size_t)Mrows * Hn];
__device__ float g_wbuf[(size_t)NB * Hn * Lseq];
__device__ float g_pq[NB * Cdim];
__device__ float g_pk[NB * Cdim];

__device__ __half g_xq16[(size_t)Mrows * Cdim];
__device__ __half g_xkv16[(size_t)Mrows * Cdim];
__device__ __half g_V16[(size_t)Mrows * Cdim];
__device__ __half g_T16[(size_t)Mrows * Cdim];
__device__ __half g_WT[5][(size_t)Cdim * Cdim];
__device__ __half g_WTb[(size_t)NB * Cdim * Cdim];   // per-batch pk-scaled Wt^T

// ---------------------------------------------------------------------------
// PTX helpers
// ---------------------------------------------------------------------------
__device__ __forceinline__ uint32_t smem_u32(const void* p) {
    uint32_t a;
    asm("{ .reg .u64 t; cvta.to.shared.u64 t, %1; cvt.u32.u64 %0, t; }" : "=r"(a) : "l"(p));
    return a;
}
__device__ __forceinline__ void cpa16(uint32_t dst, const void* src) {
    asm volatile("cp.async.cg.shared.global [%0], [%1], 16;" :: "r"(dst), "l"(src) : "memory");
}
__device__ __forceinline__ void cpa_commit() {
    asm volatile("cp.async.commit_group;" ::: "memory");
}
__device__ __forceinline__ void cpa_wait1() {
    asm volatile("cp.async.wait_group 1;" ::: "memory");
}
__device__ __forceinline__ void ldm_x4(uint32_t* r, uint32_t addr) {
    asm volatile("ldmatrix.sync.aligned.m8n8.x4.shared.b16 {%0,%1,%2,%3}, [%4];"
                 : "=r"(r[0]), "=r"(r[1]), "=r"(r[2]), "=r"(r[3]) : "r"(addr));
}
__device__ __forceinline__ void mma_fp16(float* c, const uint32_t* a, const uint32_t* b) {
    asm volatile(
        "mma.sync.aligned.m16n8k16.row.col.f32.f16.f16.f32 "
        "{%0,%1,%2,%3}, {%4,%5,%6,%7}, {%8,%9}, {%0,%1,%2,%3};"
        : "+f"(c[0]), "+f"(c[1]), "+f"(c[2]), "+f"(c[3])
        : "r"(a[0]), "r"(a[1]), "r"(a[2]), "r"(a[3]), "r"(b[0]), "r"(b[1]));
}

// ---------------------------------------------------------------------------
// HMMA GEMM: out[M,1024] = A[M,1024] @ W[1024,1024] (+epilogues)
// A fp16 row-major; W fp16 K-major (per-batch via bstride). BK=64, 3 stages.
// ---------------------------------------------------------------------------
#define ROWB   144                 // 64 fp16 = 128B data + 16B pad
#define TILEB  (128 * ROWB)        // 18432
#define STAGEB (2 * TILEB)         // A, B -> 36864
#define STAGES 3
#define SMEMB  (STAGES * STAGEB)   // 110592

__device__ __forceinline__ void issue_stage(
    uint32_t sb, int s, int chunk, int tid,
    const __half* Aw, const __half* Bw, int grow0, int ncol0)
{
    uint32_t stb = sb + (uint32_t)s * STAGEB;
    int k0 = chunk * 64;
#pragma unroll
    for (int j = 0; j < 8; j++) {
        int id = tid + j * 256;            // 0..2047
        int t4 = id >> 10;                 // operand tile 0..1
        int w  = id & 1023;
        int r  = w >> 3, c = w & 7;        // row, 16B chunk
        const __half* src = (t4 == 0) ? Aw : Bw;
        int rb = (t4 == 0) ? grow0 : ncol0;
        const void* g = src + ((size_t)(rb + r) * Cdim + k0 + c * 8);
        cpa16(stb + (uint32_t)t4 * TILEB + (uint32_t)(r * ROWB + c * 16), g);
    }
}

__global__ void __launch_bounds__(256, 2) mma_gemm(
    const __half* __restrict__ Aw, const __half* __restrict__ Bw,
    const float* __restrict__ bias, const float* __restrict__ colscale,
    const float* __restrict__ addmat,
    float* __restrict__ outf, __half* __restrict__ out16,
    size_t bstride)
{
    extern __shared__ char smem[];
    uint32_t sb = smem_u32(smem);
    int tid = threadIdx.x;
    int lane = tid & 31, wid = tid >> 5;
    int wm = wid & 1, wc = wid >> 1;           // warp 64x32 tile: 2 x 4 grid
    int bM = blockIdx.y * 128, bN = blockIdx.x * 128;
    Bw += (size_t)(bM >> 12) * bstride;        // per-batch B (0 = shared)

    float acc[4][4][4];
#pragma unroll
    for (int i = 0; i < 4; i++)
#pragma unroll
        for (int j = 0; j < 4; j++)
#pragma unroll
            for (int q = 0; q < 4; q++) acc[i][j][q] = 0.f;

    int grp = lane >> 3, l7 = lane & 7;
    uint32_t a_off = (uint32_t)((l7 + ((grp & 1) << 3)) * ROWB + ((grp >> 1) << 4));
    uint32_t b_off = (uint32_t)((l7 + ((grp >> 1) << 3)) * ROWB + ((grp & 1) << 4));

    // prologue: 2 chunks
#pragma unroll
    for (int s = 0; s < 2; s++) {
        issue_stage(sb, s, s, tid, Aw, Bw, bM, bN);
        cpa_commit();
    }

    for (int k = 0; k < 16; k++) {
        cpa_wait1();
        __syncthreads();
        if (k + 2 < 16)
            issue_stage(sb, (k + 2) % 3, k + 2, tid, Aw, Bw, bM, bN);
        cpa_commit();

        uint32_t st = sb + (uint32_t)(k % 3) * STAGEB;
#pragma unroll
        for (int kk = 0; kk < 4; kk++) {
            uint32_t kb = (uint32_t)(kk * 32);
            uint32_t bh[8];
#pragma unroll
            for (int h = 0; h < 2; h++) {
                uint32_t nrow = (uint32_t)((wc * 32 + h * 16) * ROWB);
                ldm_x4(bh + h * 4, st + TILEB + nrow + b_off + kb);
            }
#pragma unroll
            for (int mt = 0; mt < 4; mt++) {
                uint32_t mrow = (uint32_t)((wm * 64 + mt * 16) * ROWB);
                uint32_t ah[4];
                ldm_x4(ah, st + mrow + a_off + kb);
#pragma unroll
                for (int nt = 0; nt < 4; nt++)
                    mma_fp16(acc[mt][nt], ah, &bh[nt * 2]);
            }
        }
    }

    // ---------------- epilogue ----------------
    int nidx = bM >> 12;
#pragma unroll
    for (int mt = 0; mt < 4; mt++) {
        int m0 = bM + wm * 64 + mt * 16 + (lane >> 2);
#pragma unroll
        for (int nt = 0; nt < 4; nt++) {
            int n = bN + wc * 32 + nt * 8 + (lane & 3) * 2;
            float b0 = bias[n], b1 = bias[n + 1];
            float v0 = acc[mt][nt][0] + b0, v1 = acc[mt][nt][1] + b1;
            float v2 = acc[mt][nt][2] + b0, v3 = acc[mt][nt][3] + b1;
            if (colscale) {
                float s0 = colscale[nidx * Cdim + n];
                float s1 = colscale[nidx * Cdim + n + 1];
                v0 *= s0; v1 *= s1; v2 *= s0; v3 *= s1;
            }
            size_t o0 = (size_t)m0 * Cdim + n;
            size_t o1 = (size_t)(m0 + 8) * Cdim + n;
            if (addmat) {
                float2 a0 = *(const float2*)(addmat + o0);
                float2 a1 = *(const float2*)(addmat + o1);
                v0 += a0.x; v1 += a0.y; v2 += a1.x; v3 += a1.y;
            }
            if (outf) {
                *(float2*)(outf + o0) = make_float2(v0, v1);
                *(float2*)(outf + o1) = make_float2(v2, v3);
            }
            if (out16) {
                *(__half2*)(out16 + o0) =
                    __halves2half2(__float2half(v0), __float2half(v1));
                *(__half2*)(out16 + o1) =
                    __halves2half2(__float2half(v2), __float2half(v3));
            }
        }
    }
}

// ---------------------------------------------------------------------------
// fp32 -> fp16 elementwise
// ---------------------------------------------------------------------------
__global__ __launch_bounds__(256) void cvt_kernel(
    const float* __restrict__ src, __half* __restrict__ dst, int n4)
{
    int i = blockIdx.x * 256 + threadIdx.x;
    if (i >= n4) return;
    float4 x = ((const float4*)src)[i];
    __half2 a = __halves2half2(__float2half(x.x), __float2half(x.y));
    __half2 b = __halves2half2(__float2half(x.z), __float2half(x.w));
    ((__half2*)dst)[2 * i] = a;
    ((__half2*)dst)[2 * i + 1] = b;
}

// ---------------------------------------------------------------------------
// W[k][n] fp32 -> WT[n][k] fp16 (transpose-convert)
// ---------------------------------------------------------------------------
__global__ __launch_bounds__(256) void wcvt_kernel(
    const float* __restrict__ W, __half* __restrict__ T16)
{
    __shared__ float t[32][33];
    int tx = threadIdx.x & 31, ty = threadIdx.x >> 5;
    int n0 = blockIdx.x * 32, k0 = blockIdx.y * 32;
#pragma unroll
    for (int i = 0; i < 32; i += 8)
        t[ty + i][tx] = W[(size_t)(k0 + ty + i) * Cdim + n0 + tx];
    __syncthreads();
#pragma unroll
    for (int i = 0; i < 32; i += 8) {
        size_t o = (size_t)(n0 + ty + i) * Cdim + k0 + tx;
        T16[o] = __float2half(t[tx][ty + i]);
    }
}

// ---------------------------------------------------------------------------
// WTb[b][n][k] = pk[b,k] * WT[n][k]   (fold pooled-k gate into Wt operand)
// ---------------------------------------------------------------------------
__global__ __launch_bounds__(256) void wtb_kernel(
    const float* __restrict__ pk, const __half* __restrict__ wt,
    __half* __restrict__ outw)
{
    size_t i = (size_t)blockIdx.x * 256 + threadIdx.x;   // over 8*1024*512 half2
    int k2 = (int)(i & 511);
    int n  = (int)((i >> 9) & 1023);
    int b  = (int)(i >> 19);
    float2 wf = __half22float2(((const __half2*)wt)[((size_t)n << 9) | k2]);
    float s0 = pk[b * Cdim + k2 * 2];
    float s1 = pk[b * Cdim + k2 * 2 + 1];
    ((__half2*)outw)[i] = __floats2half2_rn(wf.x * s0, wf.y * s1);
}

// ---------------------------------------------------------------------------
// attention logits / softmax / pool (fp32 activations, as in R7)
// ---------------------------------------------------------------------------
__global__ __launch_bounds__(256) void attn_logits_kernel(
    const float* __restrict__ A, const float* __restrict__ W16,
    const float* __restrict__ b16, const float* __restrict__ scalevec,
    float* __restrict__ logits)
{
    int warp = threadIdx.x >> 5, lane = threadIdx.x & 31;
    int row = blockIdx.x * 8 + warp;
    int n = row >> 12;
    const float* arow = A + (size_t)row * Cdim;
    const float* sv = scalevec ? scalevec + (size_t)n * Cdim : nullptr;

    float acc[16];
#pragma unroll
    for (int h = 0; h < 16; h++) acc[h] = 0.f;

    for (int c = lane; c < Cdim; c += 32) {
        float a = arow[c];
        if (sv) a *= sv[c];
        const float4* w4 = (const float4*)(W16 + (size_t)c * 16);
        float4 w0 = w4[0], w1 = w4[1], w2 = w4[2], w3 = w4[3];
        acc[0]  = fmaf(a, w0.x, acc[0]);  acc[1]  = fmaf(a, w0.y, acc[1]);
        acc[2]  = fmaf(a, w0.z, acc[2]);  acc[3]  = fmaf(a, w0.w, acc[3]);
        acc[4]  = fmaf(a, w1.x, acc[4]);  acc[5]  = fmaf(a, w1.y, acc[5]);
        acc[6]  = fmaf(a, w1.z, acc[6]);  acc[7]  = fmaf(a, w1.w, acc[7]);
        acc[8]  = fmaf(a, w2.x, acc[8]);  acc[9]  = fmaf(a, w2.y, acc[9]);
        acc[10] = fmaf(a, w2.z, acc[10]); acc[11] = fmaf(a, w2.w, acc[11]);
        acc[12] = fmaf(a, w3.x, acc[12]); acc[13] = fmaf(a, w3.y, acc[13]);
        acc[14] = fmaf(a, w3.z, acc[14]); acc[15] = fmaf(a, w3.w, acc[15]);
    }
#pragma unroll
    for (int h = 0; h < 16; h++) {
        float v = acc[h];
#pragma unroll
        for (int o = 16; o; o >>= 1) v += __shfl_xor_sync(0xffffffffu, v, o);
        if (lane == h) logits[(size_t)row * 16 + h] = (v + b16[h]) * ATT_SCALE;
    }
}

__global__ __launch_bounds__(256) void softmax_L_kernel(
    const float* __restrict__ logits, float* __restrict__ w_out)
{
    int n = blockIdx.x / Hn, h = blockIdx.x % Hn;
    __shared__ float buf[Lseq];
    __shared__ float red[256];
    int tid = threadIdx.x;

    float m = -1e30f;
    for (int l = tid; l < Lseq; l += 256) {
        float v = logits[((size_t)n * Lseq + l) * Hn + h];
        buf[l] = v;
        m = fmaxf(m, v);
    }
    red[tid] = m; __syncthreads();
    for (int s = 128; s; s >>= 1) {
        if (tid < s) red[tid] = fmaxf(red[tid], red[tid + s]);
        __syncthreads();
    }
    m = red[0]; __syncthreads();

    float sum = 0.f;
    for (int l = tid; l < Lseq; l += 256) {
        float e = __expf(buf[l] - m);
        buf[l] = e;
        sum += e;
    }
    red[tid] = sum; __syncthreads();
    for (int s = 128; s; s >>= 1) {
        if (tid < s) red[tid] += red[tid + s];
        __syncthreads();
    }
    float inv = 1.f / red[0];

    float* wp = w_out + ((size_t)n * Hn + h) * Lseq;
    for (int l = tid; l < Lseq; l += 256) wp[l] = buf[l] * inv;
}

__global__ __launch_bounds__(1024) void pool_kernel(
    const float* __restrict__ w, const float* __restrict__ A,
    float* __restrict__ pooled)
{
    int h = blockIdx.x, n = blockIdx.y;
    int tid = threadIdx.x;
    int dh = tid & 63, g = tid >> 6;

    const float* wp = w + ((size_t)n * Hn + h) * Lseq + g * 256;
    const float* ap = A + ((size_t)(n * Lseq + g * 256)) * Cdim + h * 64 + dh;

    float a0 = 0.f, a1 = 0.f, a2 = 0.f, a3 = 0.f;
    for (int l = 0; l < 256; l += 4) {
        a0 = fmaf(wp[l + 0], ap[(size_t)(l + 0) * Cdim], a0);
        a1 = fmaf(wp[l + 1], ap[(size_t)(l + 1) * Cdim], a1);
        a2 = fmaf(wp[l + 2], ap[(size_t)(l + 2) * Cdim], a2);
        a3 = fmaf(wp[l + 3], ap[(size_t)(l + 3) * Cdim], a3);
    }
    __shared__ float red[1024];
    red[tid] = a0 + a1 + a2 + a3;
    __syncthreads();
    if (tid < 64) {
        float s = 0.f;
#pragma unroll
        for (int gg = 0; gg < 16; gg++) s += red[dh + gg * 64];
        pooled[(size_t)n * Cdim + h * 64 + dh] = s;
    }
}

// ---------------------------------------------------------------------------
// Launch: forked-stream DAG (graph-capturable event fork/join)
// ---------------------------------------------------------------------------
extern "C" void kernel_launch(void* const* d_in, const int* in_sizes, int n_in,
                              void* d_out, int out_size)
{
    const float* x_q  = (const float*)d_in[0];
    const float* x_kv = (const float*)d_in[1];
    const float* Wq   = (const float*)d_in[2];
    const float* bq   = (const float*)d_in[3];
    const float* Wqa  = (const float*)d_in[4];
    const float* bqa  = (const float*)d_in[5];
    const float* Wk   = (const float*)d_in[6];
    const float* bk   = (const float*)d_in[7];
    const float* Wka  = (const float*)d_in[8];
    const float* bka  = (const float*)d_in[9];
    const float* Wv   = (const float*)d_in[10];
    const float* bv   = (const float*)d_in[11];
    const float* Wt   = (const float*)d_in[12];
    const float* bt   = (const float*)d_in[13];
    const float* Wp   = (const float*)d_in[14];
    const float* bp   = (const float*)d_in[15];
    float* out = (float*)d_out;

    float *Qb, *Kb, *lg, *wb, *pq, *pk;
    __half *xq16, *xkv16, *V16, *T16, *WT, *WTb;
    cudaGetSymbolAddress((void**)&Qb, g_Q);
    cudaGetSymbolAddress((void**)&Kb, g_K);
    cudaGetSymbolAddress((void**)&lg, g_logits);
    cudaGetSymbolAddress((void**)&wb, g_wbuf);
    cudaGetSymbolAddress((void**)&pq, g_pq);
    cudaGetSymbolAddress((void**)&pk, g_pk);
    cudaGetSymbolAddress((void**)&xq16, g_xq16);
    cudaGetSymbolAddress((void**)&xkv16, g_xkv16);
    cudaGetSymbolAddress((void**)&V16, g_V16);
    cudaGetSymbolAddress((void**)&T16, g_T16);
    cudaGetSymbolAddress((void**)&WT, g_WT);
    cudaGetSymbolAddress((void**)&WTb, g_WTb);

    const size_t WSZ = (size_t)Cdim * Cdim;
    __half *wq16 = WT + 0 * WSZ, *wk16 = WT + 1 * WSZ, *wv16 = WT + 2 * WSZ;
    __half *wt16 = WT + 3 * WSZ, *wp16 = WT + 4 * WSZ;

    cudaFuncSetAttribute(mma_gemm, cudaFuncAttributeMaxDynamicSharedMemorySize, SMEMB);

    // fresh per call (no static guards); intentionally not destroyed
    cudaStream_t s1;
    cudaStreamCreateWithFlags(&s1, cudaStreamNonBlocking);
    cudaEvent_t evFork, evCvt, evQ, evK, evJoin;
    cudaEventCreateWithFlags(&evFork, cudaEventDisableTiming);
    cudaEventCreateWithFlags(&evCvt,  cudaEventDisableTiming);
    cudaEventCreateWithFlags(&evQ,    cudaEventDisableTiming);
    cudaEventCreateWithFlags(&evK,    cudaEventDisableTiming);
    cudaEventCreateWithFlags(&evJoin, cudaEventDisableTiming);

    int n4 = Mrows * Cdim / 4;
    dim3 wg(32, 32);
    dim3 gg(Cdim / 128, Mrows / 128);   // 8 x 256

    // ---- fork ----
    cudaEventRecord(evFork, 0);
    cudaStreamWaitEvent(s1, evFork, 0);

    // side stream: kv-side preprocessing (overlaps Q-GEMM)
    cvt_kernel<<<(n4 + 255) / 256, 256, 0, s1>>>(x_kv, xkv16, n4);
    wcvt_kernel<<<wg, 256, 0, s1>>>(Wk, wk16);
    wcvt_kernel<<<wg, 256, 0, s1>>>(Wv, wv16);
    cudaEventRecord(evCvt, s1);
    wcvt_kernel<<<wg, 256, 0, s1>>>(Wt, wt16);
    wcvt_kernel<<<wg, 256, 0, s1>>>(Wp, wp16);

    // main: Q path
    cvt_kernel<<<(n4 + 255) / 256, 256>>>(x_q, xq16, n4);
    wcvt_kernel<<<wg, 256>>>(Wq, wq16);
    mma_gemm<<<gg, 256, SMEMB>>>(xq16, wq16, bq, nullptr, nullptr, Qb, nullptr, 0);
    cudaEventRecord(evQ, 0);

    // main: K and V-raw GEMMs (V no longer needs pk)
    cudaStreamWaitEvent(0, evCvt, 0);
    mma_gemm<<<gg, 256, SMEMB>>>(xkv16, wk16, bk, nullptr, nullptr, Kb, nullptr, 0);
    cudaEventRecord(evK, 0);
    mma_gemm<<<gg, 256, SMEMB>>>(xkv16, wv16, bv, nullptr, nullptr, nullptr, V16, 0);

    // side: q-chain (overlaps K+V GEMMs)
    cudaStreamWaitEvent(s1, evQ, 0);
    attn_logits_kernel<<<Mrows / 8, 256, 0, s1>>>(Qb, Wqa, bqa, nullptr, lg);
    softmax_L_kernel<<<NB * Hn, 256, 0, s1>>>(lg, wb);
    pool_kernel<<<dim3(Hn, NB), 1024, 0, s1>>>(wb, Qb, pq);
    // side: k-chain (overlaps V GEMM)
    cudaStreamWaitEvent(s1, evK, 0);
    attn_logits_kernel<<<Mrows / 8, 256, 0, s1>>>(Kb, Wka, bka, pq, lg);
    softmax_L_kernel<<<NB * Hn, 256, 0, s1>>>(lg, wb);
    pool_kernel<<<dim3(Hn, NB), 1024, 0, s1>>>(wb, Kb, pk);
    // side: fold pk into Wt (per-batch B for T-GEMM)
    wtb_kernel<<<(NB * Cdim * (Cdim / 2)) / 256, 256, 0, s1>>>(pk, wt16, WTb);
    cudaEventRecord(evJoin, s1);

    // ---- join; finish on main ----
    cudaStreamWaitEvent(0, evJoin, 0);
    // T = Vraw @ (pk*Wt) + bt + Q
    mma_gemm<<<gg, 256, SMEMB>>>(V16, WTb, bt, nullptr, Qb, nullptr, T16, WSZ);
    // out = T @ Wp + bp
    mma_gemm<<<gg, 256, SMEMB>>>(T16, wp16, bp, nullptr, nullptr, out, nullptr, 0);
}

// round 10
// speedup vs baseline: 1.4176x; 1.1181x over previous
#include <cuda_runtime.h>
#include <cuda_fp16.h>
#include <cstdint>

#define Cdim 1024
#define Hn   16
#define NB   8
#define Lseq 4096
#define Mrows (NB * Lseq)      // 32768
#define ATT_SCALE 0.125f

// ---------------------------------------------------------------------------
// Scratch
// ---------------------------------------------------------------------------
__device__ float g_Q[(size_t)Mrows * Cdim];
__device__ float g_K[(size_t)Mrows * Cdim];
__device__ float g_logits[(size_t)Mrows * Hn];
__device__ float g_wbuf[(size_t)NB * Hn * Lseq];
__device__ float g_pq[NB * Cdim];
__device__ float g_pk[NB * Cdim];

__device__ __half g_xq16[(size_t)Mrows * Cdim];
__device__ __half g_xkv16[(size_t)Mrows * Cdim];
__device__ __half g_V16[(size_t)Mrows * Cdim];
__device__ __half g_T16[(size_t)Mrows * Cdim];
__device__ __half g_WT[5][(size_t)Cdim * Cdim];
__device__ __half g_WTb[(size_t)NB * Cdim * Cdim];   // per-batch pk-scaled Wt^T
__device__ __half g_WqaT[(size_t)128 * Cdim];        // Wqa^T zero-padded to 128 rows

// ---------------------------------------------------------------------------
// PTX helpers
// ---------------------------------------------------------------------------
__device__ __forceinline__ uint32_t smem_u32(const void* p) {
    uint32_t a;
    asm("{ .reg .u64 t; cvta.to.shared.u64 t, %1; cvt.u32.u64 %0, t; }" : "=r"(a) : "l"(p));
    return a;
}
__device__ __forceinline__ void cpa16(uint32_t dst, const void* src) {
    asm volatile("cp.async.cg.shared.global [%0], [%1], 16;" :: "r"(dst), "l"(src) : "memory");
}
__device__ __forceinline__ void cpa_commit() {
    asm volatile("cp.async.commit_group;" ::: "memory");
}
__device__ __forceinline__ void cpa_wait1() {
    asm volatile("cp.async.wait_group 1;" ::: "memory");
}
__device__ __forceinline__ void ldm_x4(uint32_t* r, uint32_t addr) {
    asm volatile("ldmatrix.sync.aligned.m8n8.x4.shared.b16 {%0,%1,%2,%3}, [%4];"
                 : "=r"(r[0]), "=r"(r[1]), "=r"(r[2]), "=r"(r[3]) : "r"(addr));
}
__device__ __forceinline__ void mma_fp16(float* c, const uint32_t* a, const uint32_t* b) {
    asm volatile(
        "mma.sync.aligned.m16n8k16.row.col.f32.f16.f16.f32 "
        "{%0,%1,%2,%3}, {%4,%5,%6,%7}, {%8,%9}, {%0,%1,%2,%3};"
        : "+f"(c[0]), "+f"(c[1]), "+f"(c[2]), "+f"(c[3])
        : "r"(a[0]), "r"(a[1]), "r"(a[2]), "r"(a[3]), "r"(b[0]), "r"(b[1]));
}

// ---------------------------------------------------------------------------
// HMMA GEMM with optional fused logits tile (cols >= Cdim come from Bw2)
// ---------------------------------------------------------------------------
#define ROWB   144                 // 64 fp16 = 128B data + 16B pad
#define TILEB  (128 * ROWB)        // 18432
#define STAGEB (2 * TILEB)         // A, B -> 36864
#define STAGES 3
#define SMEMB  (STAGES * STAGEB)   // 110592

__device__ __forceinline__ void issue_stage(
    uint32_t sb, int s, int chunk, int tid,
    const __half* Aw, const __half* Bsrc, int grow0, int ncol0)
{
    uint32_t stb = sb + (uint32_t)s * STAGEB;
    int k0 = chunk * 64;
#pragma unroll
    for (int j = 0; j < 8; j++) {
        int id = tid + j * 256;            // 0..2047
        int t4 = id >> 10;                 // operand tile 0..1
        int w  = id & 1023;
        int r  = w >> 3, c = w & 7;        // row, 16B chunk
        const __half* src = (t4 == 0) ? Aw : Bsrc;
        int rb = (t4 == 0) ? grow0 : ncol0;
        const void* g = src + ((size_t)(rb + r) * Cdim + k0 + c * 8);
        cpa16(stb + (uint32_t)t4 * TILEB + (uint32_t)(r * ROWB + c * 16), g);
    }
}

__global__ void __launch_bounds__(256, 2) mma_gemm(
    const __half* __restrict__ Aw, const __half* __restrict__ Bw,
    const __half* __restrict__ Bw2,        // logits-tile B (cols >= Cdim), or null
    const float* __restrict__ bias, const float* __restrict__ bias2,
    const float* __restrict__ colscale,
    const float* __restrict__ addmat,
    float* __restrict__ outf, __half* __restrict__ out16,
    float* __restrict__ logits_out,
    size_t bstride)
{
    extern __shared__ char smem[];
    uint32_t sb = smem_u32(smem);
    int tid = threadIdx.x;
    int lane = tid & 31, wid = tid >> 5;
    int wm = wid & 1, wc = wid >> 1;           // warp 64x32 tile: 2 x 4 grid
    int bM = blockIdx.y * 128, bN = blockIdx.x * 128;
    bool logit_tile = (bN >= Cdim);
    const __half* Bsrc;
    int ncol0;
    if (logit_tile) { Bsrc = Bw2; ncol0 = bN - Cdim; }
    else            { Bsrc = Bw + (size_t)(bM >> 12) * bstride; ncol0 = bN; }

    float acc[4][4][4];
#pragma unroll
    for (int i = 0; i < 4; i++)
#pragma unroll
        for (int j = 0; j < 4; j++)
#pragma unroll
            for (int q = 0; q < 4; q++) acc[i][j][q] = 0.f;

    int grp = lane >> 3, l7 = lane & 7;
    uint32_t a_off = (uint32_t)((l7 + ((grp & 1) << 3)) * ROWB + ((grp >> 1) << 4));
    uint32_t b_off = (uint32_t)((l7 + ((grp >> 1) << 3)) * ROWB + ((grp & 1) << 4));

    // prologue: 2 chunks
#pragma unroll
    for (int s = 0; s < 2; s++) {
        issue_stage(sb, s, s, tid, Aw, Bsrc, bM, ncol0);
        cpa_commit();
    }

    for (int k = 0; k < 16; k++) {
        cpa_wait1();
        __syncthreads();
        if (k + 2 < 16)
            issue_stage(sb, (k + 2) % 3, k + 2, tid, Aw, Bsrc, bM, ncol0);
        cpa_commit();

        uint32_t st = sb + (uint32_t)(k % 3) * STAGEB;
#pragma unroll
        for (int kk = 0; kk < 4; kk++) {
            uint32_t kb = (uint32_t)(kk * 32);
            uint32_t bh[8];
#pragma unroll
            for (int h = 0; h < 2; h++) {
                uint32_t nrow = (uint32_t)((wc * 32 + h * 16) * ROWB);
                ldm_x4(bh + h * 4, st + TILEB + nrow + b_off + kb);
            }
#pragma unroll
            for (int mt = 0; mt < 4; mt++) {
                uint32_t mrow = (uint32_t)((wm * 64 + mt * 16) * ROWB);
                uint32_t ah[4];
                ldm_x4(ah, st + mrow + a_off + kb);
#pragma unroll
                for (int nt = 0; nt < 4; nt++)
                    mma_fp16(acc[mt][nt], ah, &bh[nt * 2]);
            }
        }
    }

    // ---------------- epilogue ----------------
    if (logit_tile) {
        // only cols 0..15 of this tile are real heads: wc==0, nt<2
        if (wc == 0) {
#pragma unroll
            for (int mt = 0; mt < 4; mt++) {
                int m0 = bM + wm * 64 + mt * 16 + (lane >> 2);
#pragma unroll
                for (int nt = 0; nt < 2; nt++) {
                    int h = nt * 8 + (lane & 3) * 2;
                    float b0 = bias2[h], b1 = bias2[h + 1];
                    float2 v0 = make_float2((acc[mt][nt][0] + b0) * ATT_SCALE,
                                            (acc[mt][nt][1] + b1) * ATT_SCALE);
                    float2 v1 = make_float2((acc[mt][nt][2] + b0) * ATT_SCALE,
                                            (acc[mt][nt][3] + b1) * ATT_SCALE);
                    *(float2*)(logits_out + (size_t)m0 * Hn + h) = v0;
                    *(float2*)(logits_out + (size_t)(m0 + 8) * Hn + h) = v1;
                }
            }
        }
        return;
    }

    int nidx = bM >> 12;
#pragma unroll
    for (int mt = 0; mt < 4; mt++) {
        int m0 = bM + wm * 64 + mt * 16 + (lane >> 2);
#pragma unroll
        for (int nt = 0; nt < 4; nt++) {
            int n = bN + wc * 32 + nt * 8 + (lane & 3) * 2;
            float b0 = bias[n], b1 = bias[n + 1];
            float v0 = acc[mt][nt][0] + b0, v1 = acc[mt][nt][1] + b1;
            float v2 = acc[mt][nt][2] + b0, v3 = acc[mt][nt][3] + b1;
            if (colscale) {
                float s0 = colscale[nidx * Cdim + n];
                float s1 = colscale[nidx * Cdim + n + 1];
                v0 *= s0; v1 *= s1; v2 *= s0; v3 *= s1;
            }
            size_t o0 = (size_t)m0 * Cdim + n;
            size_t o1 = (size_t)(m0 + 8) * Cdim + n;
            if (addmat) {
                float2 a0 = *(const float2*)(addmat + o0);
                float2 a1 = *(const float2*)(addmat + o1);
                v0 += a0.x; v1 += a0.y; v2 += a1.x; v3 += a1.y;
            }
            if (outf) {
                *(float2*)(outf + o0) = make_float2(v0, v1);
                *(float2*)(outf + o1) = make_float2(v2, v3);
            }
            if (out16) {
                *(__half2*)(out16 + o0) =
                    __halves2half2(__float2half(v0), __float2half(v1));
                *(__half2*)(out16 + o1) =
                    __halves2half2(__float2half(v2), __float2half(v3));
            }
        }
    }
}

// ---------------------------------------------------------------------------
// fp32 -> fp16 elementwise
// ---------------------------------------------------------------------------
__global__ __launch_bounds__(256) void cvt_kernel(
    const float* __restrict__ src, __half* __restrict__ dst, int n4)
{
    int i = blockIdx.x * 256 + threadIdx.x;
    if (i >= n4) return;
    float4 x = ((const float4*)src)[i];
    __half2 a = __halves2half2(__float2half(x.x), __float2half(x.y));
    __half2 b = __halves2half2(__float2half(x.z), __float2half(x.w));
    ((__half2*)dst)[2 * i] = a;
    ((__half2*)dst)[2 * i + 1] = b;
}

// ---------------------------------------------------------------------------
// W[k][n] fp32 -> WT[n][k] fp16 (transpose-convert)
// ---------------------------------------------------------------------------
__global__ __launch_bounds__(256) void wcvt_kernel(
    const float* __restrict__ W, __half* __restrict__ T16)
{
    __shared__ float t[32][33];
    int tx = threadIdx.x & 31, ty = threadIdx.x >> 5;
    int n0 = blockIdx.x * 32, k0 = blockIdx.y * 32;
#pragma unroll
    for (int i = 0; i < 32; i += 8)
        t[ty + i][tx] = W[(size_t)(k0 + ty + i) * Cdim + n0 + tx];
    __syncthreads();
#pragma unroll
    for (int i = 0; i < 32; i += 8) {
        size_t o = (size_t)(n0 + ty + i) * Cdim + k0 + tx;
        T16[o] = __float2half(t[tx][ty + i]);
    }
}

// ---------------------------------------------------------------------------
// Wqa [C,16] fp32 -> WqaT [128,C] fp16 zero-padded
// ---------------------------------------------------------------------------
__global__ __launch_bounds__(256) void wqacvt_kernel(
    const float* __restrict__ Wqa, __half* __restrict__ outw)
{
    int i = blockIdx.x * 256 + threadIdx.x;   // 0..131071
    int c = i & (Cdim - 1), h = i >> 10;
    outw[(size_t)h * Cdim + c] =
        (h < Hn) ? __float2half(Wqa[c * Hn + h]) : __float2half(0.f);
}

// ---------------------------------------------------------------------------
// WTb[b][n][k] = pk[b,k] * WT[n][k]
// ---------------------------------------------------------------------------
__global__ __launch_bounds__(256) void wtb_kernel(
    const float* __restrict__ pk, const __half* __restrict__ wt,
    __half* __restrict__ outw)
{
    size_t i = (size_t)blockIdx.x * 256 + threadIdx.x;
    int k2 = (int)(i & 511);
    int n  = (int)((i >> 9) & 1023);
    int b  = (int)(i >> 19);
    float2 wf = __half22float2(((const __half2*)wt)[((size_t)n << 9) | k2]);
    float s0 = pk[b * Cdim + k2 * 2];
    float s1 = pk[b * Cdim + k2 * 2 + 1];
    ((__half2*)outw)[i] = __floats2half2_rn(wf.x * s0, wf.y * s1);
}

// ---------------------------------------------------------------------------
// attention logits (k-side only) / softmax / pool
// ---------------------------------------------------------------------------
__global__ __launch_bounds__(256) void attn_logits_kernel(
    const float* __restrict__ A, const float* __restrict__ W16,
    const float* __restrict__ b16, const float* __restrict__ scalevec,
    float* __restrict__ logits)
{
    int warp = threadIdx.x >> 5, lane = threadIdx.x & 31;
    int row = blockIdx.x * 8 + warp;
    int n = row >> 12;
    const float* arow = A + (size_t)row * Cdim;
    const float* sv = scalevec ? scalevec + (size_t)n * Cdim : nullptr;

    float acc[16];
#pragma unroll
    for (int h = 0; h < 16; h++) acc[h] = 0.f;

    for (int c = lane; c < Cdim; c += 32) {
        float a = arow[c];
        if (sv) a *= sv[c];
        const float4* w4 = (const float4*)(W16 + (size_t)c * 16);
        float4 w0 = w4[0], w1 = w4[1], w2 = w4[2], w3 = w4[3];
        acc[0]  = fmaf(a, w0.x, acc[0]);  acc[1]  = fmaf(a, w0.y, acc[1]);
        acc[2]  = fmaf(a, w0.z, acc[2]);  acc[3]  = fmaf(a, w0.w, acc[3]);
        acc[4]  = fmaf(a, w1.x, acc[4]);  acc[5]  = fmaf(a, w1.y, acc[5]);
        acc[6]  = fmaf(a, w1.z, acc[6]);  acc[7]  = fmaf(a, w1.w, acc[7]);
        acc[8]  = fmaf(a, w2.x, acc[8]);  acc[9]  = fmaf(a, w2.y, acc[9]);
        acc[10] = fmaf(a, w2.z, acc[10]); acc[11] = fmaf(a, w2.w, acc[11]);
        acc[12] = fmaf(a, w3.x, acc[12]); acc[13] = fmaf(a, w3.y, acc[13]);
        acc[14] = fmaf(a, w3.z, acc[14]); acc[15] = fmaf(a, w3.w, acc[15]);
    }
#pragma unroll
    for (int h = 0; h < 16; h++) {
        float v = acc[h];
#pragma unroll
        for (int o = 16; o; o >>= 1) v += __shfl_xor_sync(0xffffffffu, v, o);
        if (lane == h) logits[(size_t)row * 16 + h] = (v + b16[h]) * ATT_SCALE;
    }
}

__global__ __launch_bounds__(256) void softmax_L_kernel(
    const float* __restrict__ logits, float* __restrict__ w_out)
{
    int n = blockIdx.x / Hn, h = blockIdx.x % Hn;
    __shared__ float buf[Lseq];
    __shared__ float red[256];
    int tid = threadIdx.x;

    float m = -1e30f;
    for (int l = tid; l < Lseq; l += 256) {
        float v = logits[((size_t)n * Lseq + l) * Hn + h];
        buf[l] = v;
        m = fmaxf(m, v);
    }
    red[tid] = m; __syncthreads();
    for (int s = 128; s; s >>= 1) {
        if (tid < s) red[tid] = fmaxf(red[tid], red[tid + s]);
        __syncthreads();
    }
    m = red[0]; __syncthreads();

    float sum = 0.f;
    for (int l = tid; l < Lseq; l += 256) {
        float e = __expf(buf[l] - m);
        buf[l] = e;
        sum += e;
    }
    red[tid] = sum; __syncthreads();
    for (int s = 128; s; s >>= 1) {
        if (tid < s) red[tid] += red[tid + s];
        __syncthreads();
    }
    float inv = 1.f / red[0];

    float* wp = w_out + ((size_t)n * Hn + h) * Lseq;
    for (int l = tid; l < Lseq; l += 256) wp[l] = buf[l] * inv;
}

__global__ __launch_bounds__(1024) void pool_kernel(
    const float* __restrict__ w, const float* __restrict__ A,
    float* __restrict__ pooled)
{
    int h = blockIdx.x, n = blockIdx.y;
    int tid = threadIdx.x;
    int dh = tid & 63, g = tid >> 6;

    const float* wp = w + ((size_t)n * Hn + h) * Lseq + g * 256;
    const float* ap = A + ((size_t)(n * Lseq + g * 256)) * Cdim + h * 64 + dh;

    float a0 = 0.f, a1 = 0.f, a2 = 0.f, a3 = 0.f;
    for (int l = 0; l < 256; l += 4) {
        a0 = fmaf(wp[l + 0], ap[(size_t)(l + 0) * Cdim], a0);
        a1 = fmaf(wp[l + 1], ap[(size_t)(l + 1) * Cdim], a1);
        a2 = fmaf(wp[l + 2], ap[(size_t)(l + 2) * Cdim], a2);
        a3 = fmaf(wp[l + 3], ap[(size_t)(l + 3) * Cdim], a3);
    }
    __shared__ float red[1024];
    red[tid] = a0 + a1 + a2 + a3;
    __syncthreads();
    if (tid < 64) {
        float s = 0.f;
#pragma unroll
        for (int gg = 0; gg < 16; gg++) s += red[dh + gg * 64];
        pooled[(size_t)n * Cdim + h * 64 + dh] = s;
    }
}

// ---------------------------------------------------------------------------
// Launch: forked-stream DAG with fused q-logits
// ---------------------------------------------------------------------------
extern "C" void kernel_launch(void* const* d_in, const int* in_sizes, int n_in,
                              void* d_out, int out_size)
{
    const float* x_q  = (const float*)d_in[0];
    const float* x_kv = (const float*)d_in[1];
    const float* Wq   = (const float*)d_in[2];
    const float* bq   = (const float*)d_in[3];
    const float* Wqa  = (const float*)d_in[4];
    const float* bqa  = (const float*)d_in[5];
    const float* Wk   = (const float*)d_in[6];
    const float* bk   = (const float*)d_in[7];
    const float* Wka  = (const float*)d_in[8];
    const float* bka  = (const float*)d_in[9];
    const float* Wv   = (const float*)d_in[10];
    const float* bv   = (const float*)d_in[11];
    const float* Wt   = (const float*)d_in[12];
    const float* bt   = (const float*)d_in[13];
    const float* Wp   = (const float*)d_in[14];
    const float* bp   = (const float*)d_in[15];
    float* out = (float*)d_out;

    float *Qb, *Kb, *lg, *wb, *pq, *pk;
    __half *xq16, *xkv16, *V16, *T16, *WT, *WTb, *WqaT;
    cudaGetSymbolAddress((void**)&Qb, g_Q);
    cudaGetSymbolAddress((void**)&Kb, g_K);
    cudaGetSymbolAddress((void**)&lg, g_logits);
    cudaGetSymbolAddress((void**)&wb, g_wbuf);
    cudaGetSymbolAddress((void**)&pq, g_pq);
    cudaGetSymbolAddress((void**)&pk, g_pk);
    cudaGetSymbolAddress((void**)&xq16, g_xq16);
    cudaGetSymbolAddress((void**)&xkv16, g_xkv16);
    cudaGetSymbolAddress((void**)&V16, g_V16);
    cudaGetSymbolAddress((void**)&T16, g_T16);
    cudaGetSymbolAddress((void**)&WT, g_WT);
    cudaGetSymbolAddress((void**)&WTb, g_WTb);
    cudaGetSymbolAddress((void**)&WqaT, g_WqaT);

    const size_t WSZ = (size_t)Cdim * Cdim;
    __half *wq16 = WT + 0 * WSZ, *wk16 = WT + 1 * WSZ, *wv16 = WT + 2 * WSZ;
    __half *wt16 = WT + 3 * WSZ, *wp16 = WT + 4 * WSZ;

    cudaFuncSetAttribute(mma_gemm, cudaFuncAttributeMaxDynamicSharedMemorySize, SMEMB);

    cudaStream_t s1;
    cudaStreamCreateWithFlags(&s1, cudaStreamNonBlocking);
    cudaEvent_t evFork, evCvt, evQ, evK, evJoin;
    cudaEventCreateWithFlags(&evFork, cudaEventDisableTiming);
    cudaEventCreateWithFlags(&evCvt,  cudaEventDisableTiming);
    cudaEventCreateWithFlags(&evQ,    cudaEventDisableTiming);
    cudaEventCreateWithFlags(&evK,    cudaEventDisableTiming);
    cudaEventCreateWithFlags(&evJoin, cudaEventDisableTiming);

    int n4 = Mrows * Cdim / 4;
    dim3 wg(32, 32);
    dim3 gg8(8, Mrows / 128);    // N=1024
    dim3 gg9(9, Mrows / 128);    // N=1152 (fused q-logits)

    // ---- fork ----
    cudaEventRecord(evFork, 0);
    cudaStreamWaitEvent(s1, evFork, 0);

    // side: kv preprocessing (overlaps Q GEMM)
    cvt_kernel<<<(n4 + 255) / 256, 256, 0, s1>>>(x_kv, xkv16, n4);
    wcvt_kernel<<<wg, 256, 0, s1>>>(Wk, wk16);
    wcvt_kernel<<<wg, 256, 0, s1>>>(Wv, wv16);
    cudaEventRecord(evCvt, s1);
    wcvt_kernel<<<wg, 256, 0, s1>>>(Wt, wt16);
    wcvt_kernel<<<wg, 256, 0, s1>>>(Wp, wp16);

    // main: Q path with fused q-logits
    cvt_kernel<<<(n4 + 255) / 256, 256>>>(x_q, xq16, n4);
    wcvt_kernel<<<wg, 256>>>(Wq, wq16);
    wqacvt_kernel<<<(128 * Cdim) / 256, 256>>>(Wqa, WqaT);
    mma_gemm<<<gg9, 256, SMEMB>>>(xq16, wq16, WqaT, bq, bqa, nullptr, nullptr,
                                  Qb, nullptr, lg, 0);
    cudaEventRecord(evQ, 0);

    // main: K then V GEMMs
    cudaStreamWaitEvent(0, evCvt, 0);
    mma_gemm<<<gg8, 256, SMEMB>>>(xkv16, wk16, nullptr, bk, nullptr, nullptr,
                                  nullptr, Kb, nullptr, nullptr, 0);
    cudaEventRecord(evK, 0);
    mma_gemm<<<gg8, 256, SMEMB>>>(xkv16, wv16, nullptr, bv, nullptr, nullptr,
                                  nullptr, nullptr, V16, nullptr, 0);

    // side: q-chain (overlaps K GEMM)
    cudaStreamWaitEvent(s1, evQ, 0);
    softmax_L_kernel<<<NB * Hn, 256, 0, s1>>>(lg, wb);
    pool_kernel<<<dim3(Hn, NB), 1024, 0, s1>>>(wb, Qb, pq);
    // side: k-chain (overlaps V GEMM)
    cudaStreamWaitEvent(s1, evK, 0);
    attn_logits_kernel<<<Mrows / 8, 256, 0, s1>>>(Kb, Wka, bka, pq, lg);
    softmax_L_kernel<<<NB * Hn, 256, 0, s1>>>(lg, wb);
    pool_kernel<<<dim3(Hn, NB), 1024, 0, s1>>>(wb, Kb, pk);
    wtb_kernel<<<(NB * Cdim * (Cdim / 2)) / 256, 256, 0, s1>>>(pk, wt16, WTb);
    cudaEventRecord(evJoin, s1);

    // ---- join ----
    cudaStreamWaitEvent(0, evJoin, 0);
    // T = Vraw @ (pk*Wt) + bt + Q
    mma_gemm<<<gg8, 256, SMEMB>>>(V16, WTb, nullptr, bt, nullptr, nullptr,
                                  Qb, nullptr, T16, nullptr, WSZ);
    // out = T @ Wp + bp
    mma_gemm<<<gg8, 256, SMEMB>>>(T16, wp16, nullptr, bp, nullptr, nullptr,
                                  nullptr, out, nullptr, nullptr, 0);
}

// round 11
// speedup vs baseline: 1.5624x; 1.1021x over previous
#include <cuda_runtime.h>
#include <cuda_fp16.h>
#include <cstdint>

#define Cdim 1024
#define Hn   16
#define NB   8
#define Lseq 4096
#define Mrows (NB * Lseq)      // 32768
#define ATT_SCALE 0.125f

// ---------------------------------------------------------------------------
// Scratch
// ---------------------------------------------------------------------------
__device__ float g_Q[(size_t)Mrows * Cdim];
__device__ float g_K[(size_t)Mrows * Cdim];
__device__ float g_logits[(size_t)Mrows * Hn];
__device__ float g_wbuf[(size_t)NB * Hn * Lseq];
__device__ float g_pq[NB * Cdim];
__device__ float g_pk[NB * Cdim];
__device__ float g_cb[NB * Cdim];
__device__ float g_zeros[Cdim];                      // stays zero

__device__ __half g_xq16[(size_t)Mrows * Cdim];
__device__ __half g_xkv16[(size_t)Mrows * Cdim];
__device__ __half g_wq16[(size_t)Cdim * Cdim];       // K-major
__device__ __half g_wk16[(size_t)Cdim * Cdim];       // K-major
__device__ __half g_wp16[(size_t)Cdim * Cdim];       // K-major
__device__ __half g_wqrm[(size_t)Cdim * Cdim];       // plain row-major
__device__ __half g_wtrm[(size_t)Cdim * Cdim];
__device__ __half g_wvrm[(size_t)Cdim * Cdim];
__device__ __half g_wtwp[(size_t)Cdim * Cdim];       // [n][k] = WtWp[k,n]
__device__ __half g_g16[(size_t)Cdim * Cdim];        // [n][k] = WqWp[k,n]
__device__ __half g_Ab[(size_t)NB * Cdim * Cdim];    // pk-scaled wtwp rows
__device__ __half g_Mb[(size_t)NB * Cdim * Cdim];    // per-batch final B
__device__ __half g_WqaT[(size_t)128 * Cdim];        // Wqa^T zero-padded

// ---------------------------------------------------------------------------
// PTX helpers
// ---------------------------------------------------------------------------
__device__ __forceinline__ uint32_t smem_u32(const void* p) {
    uint32_t a;
    asm("{ .reg .u64 t; cvta.to.shared.u64 t, %1; cvt.u32.u64 %0, t; }" : "=r"(a) : "l"(p));
    return a;
}
__device__ __forceinline__ void cpa16(uint32_t dst, const void* src) {
    asm volatile("cp.async.cg.shared.global [%0], [%1], 16;" :: "r"(dst), "l"(src) : "memory");
}
__device__ __forceinline__ void cpa_commit() {
    asm volatile("cp.async.commit_group;" ::: "memory");
}
__device__ __forceinline__ void cpa_wait1() {
    asm volatile("cp.async.wait_group 1;" ::: "memory");
}
__device__ __forceinline__ void ldm_x4(uint32_t* r, uint32_t addr) {
    asm volatile("ldmatrix.sync.aligned.m8n8.x4.shared.b16 {%0,%1,%2,%3}, [%4];"
                 : "=r"(r[0]), "=r"(r[1]), "=r"(r[2]), "=r"(r[3]) : "r"(addr));
}
__device__ __forceinline__ void mma_fp16(float* c, const uint32_t* a, const uint32_t* b) {
    asm volatile(
        "mma.sync.aligned.m16n8k16.row.col.f32.f16.f16.f32 "
        "{%0,%1,%2,%3}, {%4,%5,%6,%7}, {%8,%9}, {%0,%1,%2,%3};"
        : "+f"(c[0]), "+f"(c[1]), "+f"(c[2]), "+f"(c[3])
        : "r"(a[0]), "r"(a[1]), "r"(a[2]), "r"(a[3]), "r"(b[0]), "r"(b[1]));
}

// ---------------------------------------------------------------------------
// HMMA GEMM, optional fused logits tile (cols >= Cdim, slim compute)
// ---------------------------------------------------------------------------
#define ROWB   144
#define TILEB  (128 * ROWB)
#define STAGEB (2 * TILEB)
#define STAGES 3
#define SMEMB  (STAGES * STAGEB)   // 110592

__device__ __forceinline__ void issue_stage(
    uint32_t sb, int s, int chunk, int tid,
    const __half* Aw, const __half* Bsrc, int grow0, int ncol0)
{
    uint32_t stb = sb + (uint32_t)s * STAGEB;
    int k0 = chunk * 64;
#pragma unroll
    for (int j = 0; j < 8; j++) {
        int id = tid + j * 256;
        int t4 = id >> 10;
        int w  = id & 1023;
        int r  = w >> 3, c = w & 7;
        const __half* src = (t4 == 0) ? Aw : Bsrc;
        int rb = (t4 == 0) ? grow0 : ncol0;
        const void* g = src + ((size_t)(rb + r) * Cdim + k0 + c * 8);
        cpa16(stb + (uint32_t)t4 * TILEB + (uint32_t)(r * ROWB + c * 16), g);
    }
}

__global__ void __launch_bounds__(256, 2) mma_gemm(
    const __half* __restrict__ Aw, const __half* __restrict__ Bw,
    const __half* __restrict__ Bw2,
    const float* __restrict__ bias, int bias_batched,
    const float* __restrict__ bias2,
    const float* __restrict__ addmat,
    float* __restrict__ outf, __half* __restrict__ out16,
    float* __restrict__ logits_out,
    size_t bstride)
{
    extern __shared__ char smem[];
    uint32_t sb = smem_u32(smem);
    int tid = threadIdx.x;
    int lane = tid & 31, wid = tid >> 5;
    int wm = wid & 1, wc = wid >> 1;
    int bM = blockIdx.y * 128, bN = blockIdx.x * 128;
    bool logit_tile = (bN >= Cdim);
    const __half* Bsrc;
    int ncol0;
    if (logit_tile) { Bsrc = Bw2; ncol0 = bN - Cdim; }
    else            { Bsrc = Bw + (size_t)(bM >> 12) * bstride; ncol0 = bN; }

    float acc[4][4][4];
#pragma unroll
    for (int i = 0; i < 4; i++)
#pragma unroll
        for (int j = 0; j < 4; j++)
#pragma unroll
            for (int q = 0; q < 4; q++) acc[i][j][q] = 0.f;

    int grp = lane >> 3, l7 = lane & 7;
    uint32_t a_off = (uint32_t)((l7 + ((grp & 1) << 3)) * ROWB + ((grp >> 1) << 4));
    uint32_t b_off = (uint32_t)((l7 + ((grp >> 1) << 3)) * ROWB + ((grp & 1) << 4));

#pragma unroll
    for (int s = 0; s < 2; s++) {
        issue_stage(sb, s, s, tid, Aw, Bsrc, bM, ncol0);
        cpa_commit();
    }

    for (int k = 0; k < 16; k++) {
        cpa_wait1();
        __syncthreads();
        if (k + 2 < 16)
            issue_stage(sb, (k + 2) % 3, k + 2, tid, Aw, Bsrc, bM, ncol0);
        cpa_commit();

        uint32_t st = sb + (uint32_t)(k % 3) * STAGEB;
        if (!logit_tile) {
#pragma unroll
            for (int kk = 0; kk < 4; kk++) {
                uint32_t kb = (uint32_t)(kk * 32);
                uint32_t bh[8];
#pragma unroll
                for (int h = 0; h < 2; h++) {
                    uint32_t nrow = (uint32_t)((wc * 32 + h * 16) * ROWB);
                    ldm_x4(bh + h * 4, st + TILEB + nrow + b_off + kb);
                }
#pragma unroll
                for (int mt = 0; mt < 4; mt++) {
                    uint32_t mrow = (uint32_t)((wm * 64 + mt * 16) * ROWB);
                    uint32_t ah[4];
                    ldm_x4(ah, st + mrow + a_off + kb);
#pragma unroll
                    for (int nt = 0; nt < 4; nt++)
                        mma_fp16(acc[mt][nt], ah, &bh[nt * 2]);
                }
            }
        } else if (wc == 0) {   // slim: only cols 0..15 matter
#pragma unroll
            for (int kk = 0; kk < 4; kk++) {
                uint32_t kb = (uint32_t)(kk * 32);
                uint32_t bh[4];
                ldm_x4(bh, st + TILEB + b_off + kb);
#pragma unroll
                for (int mt = 0; mt < 4; mt++) {
                    uint32_t mrow = (uint32_t)((wm * 64 + mt * 16) * ROWB);
                    uint32_t ah[4];
                    ldm_x4(ah, st + mrow + a_off + kb);
                    mma_fp16(acc[mt][0], ah, &bh[0]);
                    mma_fp16(acc[mt][1], ah, &bh[2]);
                }
            }
        }
    }

    // ---------------- epilogue ----------------
    if (logit_tile) {
        if (wc == 0) {
#pragma unroll
            for (int mt = 0; mt < 4; mt++) {
                int m0 = bM + wm * 64 + mt * 16 + (lane >> 2);
#pragma unroll
                for (int nt = 0; nt < 2; nt++) {
                    int h = nt * 8 + (lane & 3) * 2;
                    float b0 = bias2[h], b1 = bias2[h + 1];
                    float2 v0 = make_float2((acc[mt][nt][0] + b0) * ATT_SCALE,
                                            (acc[mt][nt][1] + b1) * ATT_SCALE);
                    float2 v1 = make_float2((acc[mt][nt][2] + b0) * ATT_SCALE,
                                            (acc[mt][nt][3] + b1) * ATT_SCALE);
                    *(float2*)(logits_out + (size_t)m0 * Hn + h) = v0;
                    *(float2*)(logits_out + (size_t)(m0 + 8) * Hn + h) = v1;
                }
            }
        }
        return;
    }

    int nidx = bM >> 12;
    const float* bptr = bias + (bias_batched ? (size_t)nidx * Cdim : 0);
#pragma unroll
    for (int mt = 0; mt < 4; mt++) {
        int m0 = bM + wm * 64 + mt * 16 + (lane >> 2);
#pragma unroll
        for (int nt = 0; nt < 4; nt++) {
            int n = bN + wc * 32 + nt * 8 + (lane & 3) * 2;
            float b0 = bptr[n], b1 = bptr[n + 1];
            float v0 = acc[mt][nt][0] + b0, v1 = acc[mt][nt][1] + b1;
            float v2 = acc[mt][nt][2] + b0, v3 = acc[mt][nt][3] + b1;
            size_t o0 = (size_t)m0 * Cdim + n;
            size_t o1 = (size_t)(m0 + 8) * Cdim + n;
            if (addmat) {
                float2 a0 = *(const float2*)(addmat + o0);
                float2 a1 = *(const float2*)(addmat + o1);
                v0 += a0.x; v1 += a0.y; v2 += a1.x; v3 += a1.y;
            }
            if (outf) {
                *(float2*)(outf + o0) = make_float2(v0, v1);
                *(float2*)(outf + o1) = make_float2(v2, v3);
            }
            if (out16) {
                *(__half2*)(out16 + o0) =
                    __halves2half2(__float2half(v0), __float2half(v1));
                *(__half2*)(out16 + o1) =
                    __halves2half2(__float2half(v2), __float2half(v3));
            }
        }
    }
}

// ---------------------------------------------------------------------------
// fp32 -> fp16 elementwise
// ---------------------------------------------------------------------------
__global__ __launch_bounds__(256) void cvt_kernel(
    const float* __restrict__ src, __half* __restrict__ dst, int n4)
{
    int i = blockIdx.x * 256 + threadIdx.x;
    if (i >= n4) return;
    float4 x = ((const float4*)src)[i];
    ((__half2*)dst)[2 * i]     = __halves2half2(__float2half(x.x), __float2half(x.y));
    ((__half2*)dst)[2 * i + 1] = __halves2half2(__float2half(x.z), __float2half(x.w));
}

// ---------------------------------------------------------------------------
// W[k][n] fp32 -> WT[n][k] fp16 (transpose-convert)
// ---------------------------------------------------------------------------
__global__ __launch_bounds__(256) void wcvt_kernel(
    const float* __restrict__ W, __half* __restrict__ T16)
{
    __shared__ float t[32][33];
    int tx = threadIdx.x & 31, ty = threadIdx.x >> 5;
    int n0 = blockIdx.x * 32, k0 = blockIdx.y * 32;
#pragma unroll
    for (int i = 0; i < 32; i += 8)
        t[ty + i][tx] = W[(size_t)(k0 + ty + i) * Cdim + n0 + tx];
    __syncthreads();
#pragma unroll
    for (int i = 0; i < 32; i += 8) {
        size_t o = (size_t)(n0 + ty + i) * Cdim + k0 + tx;
        T16[o] = __float2half(t[tx][ty + i]);
    }
}

// ---------------------------------------------------------------------------
// Wqa [C,16] fp32 -> WqaT [128,C] fp16 zero-padded
// ---------------------------------------------------------------------------
__global__ __launch_bounds__(256) void wqacvt_kernel(
    const float* __restrict__ Wqa, __half* __restrict__ outw)
{
    int i = blockIdx.x * 256 + threadIdx.x;
    int c = i & (Cdim - 1), h = i >> 10;
    outw[(size_t)h * Cdim + c] =
        (h < Hn) ? __float2half(Wqa[c * Hn + h]) : __float2half(0.f);
}

// ---------------------------------------------------------------------------
// out[b][n][k] = pk[b,k] * src[n][k]
// ---------------------------------------------------------------------------
__global__ __launch_bounds__(256) void wtb_kernel(
    const float* __restrict__ pk, const __half* __restrict__ src,
    __half* __restrict__ outw)
{
    size_t i = (size_t)blockIdx.x * 256 + threadIdx.x;
    int k2 = (int)(i & 511);
    int n  = (int)((i >> 9) & 1023);
    int b  = (int)(i >> 19);
    float2 wf = __half22float2(((const __half2*)src)[((size_t)n << 9) | k2]);
    float s0 = pk[b * Cdim + k2 * 2];
    float s1 = pk[b * Cdim + k2 * 2 + 1];
    ((__half2*)outw)[i] = __floats2half2_rn(wf.x * s0, wf.y * s1);
}

// ---------------------------------------------------------------------------
// cb[b][n] = sum_j wtwp[n][j]*bv[j]*pk[b,j] + sum_j wp16[n][j]*(bt[j]+bq[j]) + bp[n]
// ---------------------------------------------------------------------------
__global__ __launch_bounds__(256) void cb_kernel(
    const float* __restrict__ pk, const __half* __restrict__ wtwp,
    const __half* __restrict__ wp16,
    const float* __restrict__ bv, const float* __restrict__ bt,
    const float* __restrict__ bq, const float* __restrict__ bp,
    float* __restrict__ cb)
{
    int warp = threadIdx.x >> 5, lane = threadIdx.x & 31;
    int idx = blockIdx.x * 8 + warp;       // 0..8191
    int b = idx >> 10, n = idx & 1023;
    float s = 0.f;
    for (int j = lane; j < Cdim; j += 32) {
        s += __half2float(wtwp[(size_t)n * Cdim + j]) * bv[j] * pk[b * Cdim + j];
        s += __half2float(wp16[(size_t)n * Cdim + j]) * (bt[j] + bq[j]);
    }
#pragma unroll
    for (int o = 16; o; o >>= 1) s += __shfl_xor_sync(0xffffffffu, s, o);
    if (lane == 0) cb[b * Cdim + n] = s + bp[n];
}

// ---------------------------------------------------------------------------
// attention logits (k-side) / softmax / pool
// ---------------------------------------------------------------------------
__global__ __launch_bounds__(256) void attn_logits_kernel(
    const float* __restrict__ A, const float* __restrict__ W16,
    const float* __restrict__ b16, const float* __restrict__ scalevec,
    float* __restrict__ logits)
{
    int warp = threadIdx.x >> 5, lane = threadIdx.x & 31;
    int row = blockIdx.x * 8 + warp;
    int n = row >> 12;
    const float* arow = A + (size_t)row * Cdim;
    const float* sv = scalevec ? scalevec + (size_t)n * Cdim : nullptr;

    float acc[16];
#pragma unroll
    for (int h = 0; h < 16; h++) acc[h] = 0.f;

    for (int c = lane; c < Cdim; c += 32) {
        float a = arow[c];
        if (sv) a *= sv[c];
        const float4* w4 = (const float4*)(W16 + (size_t)c * 16);
        float4 w0 = w4[0], w1 = w4[1], w2 = w4[2], w3 = w4[3];
        acc[0]  = fmaf(a, w0.x, acc[0]);  acc[1]  = fmaf(a, w0.y, acc[1]);
        acc[2]  = fmaf(a, w0.z, acc[2]);  acc[3]  = fmaf(a, w0.w, acc[3]);
        acc[4]  = fmaf(a, w1.x, acc[4]);  acc[5]  = fmaf(a, w1.y, acc[5]);
        acc[6]  = fmaf(a, w1.z, acc[6]);  acc[7]  = fmaf(a, w1.w, acc[7]);
        acc[8]  = fmaf(a, w2.x, acc[8]);  acc[9]  = fmaf(a, w2.y, acc[9]);
        acc[10] = fmaf(a, w2.z, acc[10]); acc[11] = fmaf(a, w2.w, acc[11]);
        acc[12] = fmaf(a, w3.x, acc[12]); acc[13] = fmaf(a, w3.y, acc[13]);
        acc[14] = fmaf(a, w3.z, acc[14]); acc[15] = fmaf(a, w3.w, acc[15]);
    }
#pragma unroll
    for (int h = 0; h < 16; h++) {
        float v = acc[h];
#pragma unroll
        for (int o = 16; o; o >>= 1) v += __shfl_xor_sync(0xffffffffu, v, o);
        if (lane == h) logits[(size_t)row * 16 + h] = (v + b16[h]) * ATT_SCALE;
    }
}

__global__ __launch_bounds__(256) void softmax_L_kernel(
    const float* __restrict__ logits, float* __restrict__ w_out)
{
    int n = blockIdx.x / Hn, h = blockIdx.x % Hn;
    __shared__ float buf[Lseq];
    __shared__ float red[256];
    int tid = threadIdx.x;

    float m = -1e30f;
    for (int l = tid; l < Lseq; l += 256) {
        float v = logits[((size_t)n * Lseq + l) * Hn + h];
        buf[l] = v;
        m = fmaxf(m, v);
    }
    red[tid] = m; __syncthreads();
    for (int s = 128; s; s >>= 1) {
        if (tid < s) red[tid] = fmaxf(red[tid], red[tid + s]);
        __syncthreads();
    }
    m = red[0]; __syncthreads();

    float sum = 0.f;
    for (int l = tid; l < Lseq; l += 256) {
        float e = __expf(buf[l] - m);
        buf[l] = e;
        sum += e;
    }
    red[tid] = sum; __syncthreads();
    for (int s = 128; s; s >>= 1) {
        if (tid < s) red[tid] += red[tid + s];
        __syncthreads();
    }
    float inv = 1.f / red[0];

    float* wp = w_out + ((size_t)n * Hn + h) * Lseq;
    for (int l = tid; l < Lseq; l += 256) wp[l] = buf[l] * inv;
}

__global__ __launch_bounds__(1024) void pool_kernel(
    const float* __restrict__ w, const float* __restrict__ A,
    float* __restrict__ pooled)
{
    int h = blockIdx.x, n = blockIdx.y;
    int tid = threadIdx.x;
    int dh = tid & 63, g = tid >> 6;

    const float* wp = w + ((size_t)n * Hn + h) * Lseq + g * 256;
    const float* ap = A + ((size_t)(n * Lseq + g * 256)) * Cdim + h * 64 + dh;

    float a0 = 0.f, a1 = 0.f, a2 = 0.f, a3 = 0.f;
    for (int l = 0; l < 256; l += 4) {
        a0 = fmaf(wp[l + 0], ap[(size_t)(l + 0) * Cdim], a0);
        a1 = fmaf(wp[l + 1], ap[(size_t)(l + 1) * Cdim], a1);
        a2 = fmaf(wp[l + 2], ap[(size_t)(l + 2) * Cdim], a2);
        a3 = fmaf(wp[l + 3], ap[(size_t)(l + 3) * Cdim], a3);
    }
    __shared__ float red[1024];
    red[tid] = a0 + a1 + a2 + a3;
    __syncthreads();
    if (tid < 64) {
        float s = 0.f;
#pragma unroll
        for (int gg = 0; gg < 16; gg++) s += red[dh + gg * 64];
        pooled[(size_t)n * Cdim + h * 64 + dh] = s;
    }
}

// ---------------------------------------------------------------------------
// Launch
// ---------------------------------------------------------------------------
extern "C" void kernel_launch(void* const* d_in, const int* in_sizes, int n_in,
                              void* d_out, int out_size)
{
    const float* x_q  = (const float*)d_in[0];
    const float* x_kv = (const float*)d_in[1];
    const float* Wq   = (const float*)d_in[2];
    const float* bq   = (const float*)d_in[3];
    const float* Wqa  = (const float*)d_in[4];
    const float* bqa  = (const float*)d_in[5];
    const float* Wk   = (const float*)d_in[6];
    const float* bk   = (const float*)d_in[7];
    const float* Wka  = (const float*)d_in[8];
    const float* bka  = (const float*)d_in[9];
    const float* Wv   = (const float*)d_in[10];
    const float* bv   = (const float*)d_in[11];
    const float* Wt   = (const float*)d_in[12];
    const float* bt   = (const float*)d_in[13];
    const float* Wp   = (const float*)d_in[14];
    const float* bp   = (const float*)d_in[15];
    float* out = (float*)d_out;

    float *Qb, *Kb, *lg, *wb, *pq, *pk, *cbv, *zeros;
    __half *xq16, *xkv16, *wq16, *wk16, *wp16, *wqrm, *wtrm, *wvrm;
    __half *wtwp, *g16, *Ab, *Mb, *WqaT;
    cudaGetSymbolAddress((void**)&Qb, g_Q);
    cudaGetSymbolAddress((void**)&Kb, g_K);
    cudaGetSymbolAddress((void**)&lg, g_logits);
    cudaGetSymbolAddress((void**)&wb, g_wbuf);
    cudaGetSymbolAddress((void**)&pq, g_pq);
    cudaGetSymbolAddress((void**)&pk, g_pk);
    cudaGetSymbolAddress((void**)&cbv, g_cb);
    cudaGetSymbolAddress((void**)&zeros, g_zeros);
    cudaGetSymbolAddress((void**)&xq16, g_xq16);
    cudaGetSymbolAddress((void**)&xkv16, g_xkv16);
    cudaGetSymbolAddress((void**)&wq16, g_wq16);
    cudaGetSymbolAddress((void**)&wk16, g_wk16);
    cudaGetSymbolAddress((void**)&wp16, g_wp16);
    cudaGetSymbolAddress((void**)&wqrm, g_wqrm);
    cudaGetSymbolAddress((void**)&wtrm, g_wtrm);
    cudaGetSymbolAddress((void**)&wvrm, g_wvrm);
    cudaGetSymbolAddress((void**)&wtwp, g_wtwp);
    cudaGetSymbolAddress((void**)&g16, g_g16);
    cudaGetSymbolAddress((void**)&Ab, g_Ab);
    cudaGetSymbolAddress((void**)&Mb, g_Mb);
    cudaGetSymbolAddress((void**)&WqaT, g_WqaT);

    const size_t WSZ = (size_t)Cdim * Cdim;
    cudaFuncSetAttribute(mma_gemm, cudaFuncAttributeMaxDynamicSharedMemorySize, SMEMB);

    cudaStream_t s1;
    cudaStreamCreateWithFlags(&s1, cudaStreamNonBlocking);
    cudaEvent_t evFork, evCvt, evG, evQ, evK, evJoin;
    cudaEventCreateWithFlags(&evFork, cudaEventDisableTiming);
    cudaEventCreateWithFlags(&evCvt,  cudaEventDisableTiming);
    cudaEventCreateWithFlags(&evG,    cudaEventDisableTiming);
    cudaEventCreateWithFlags(&evQ,    cudaEventDisableTiming);
    cudaEventCreateWithFlags(&evK,    cudaEventDisableTiming);
    cudaEventCreateWithFlags(&evJoin, cudaEventDisableTiming);

    int n4 = Mrows * Cdim / 4;
    int w4 = Cdim * Cdim / 4;
    dim3 wg(32, 32);
    dim3 gg8(8, Mrows / 128);    // big GEMMs, N=1024
    dim3 gg9(9, Mrows / 128);    // Q with fused logits
    dim3 ggw(8, 8);              // weight GEMMs, M=1024
    dim3 ggm(8, 64);             // Mb GEMM, M=8192

    // ---- fork ----
    cudaEventRecord(evFork, 0);
    cudaStreamWaitEvent(s1, evFork, 0);

    // s1: kv + weight-chain prep
    cvt_kernel<<<(n4 + 255) / 256, 256, 0, s1>>>(x_kv, xkv16, n4);
    wcvt_kernel<<<wg, 256, 0, s1>>>(Wk, wk16);
    cudaEventRecord(evCvt, s1);
    wcvt_kernel<<<wg, 256, 0, s1>>>(Wp, wp16);
    cvt_kernel<<<(w4 + 255) / 256, 256, 0, s1>>>(Wt, wtrm, w4);
    cvt_kernel<<<(w4 + 255) / 256, 256, 0, s1>>>(Wq, wqrm, w4);
    cvt_kernel<<<(w4 + 255) / 256, 256, 0, s1>>>(Wv, wvrm, w4);
    // wtwp[n][k] = WtWp[k,n]
    mma_gemm<<<ggw, 256, SMEMB, s1>>>(wp16, wtrm, nullptr, zeros, 0, nullptr,
                                      nullptr, nullptr, wtwp, nullptr, 0);
    // g16[n][k] = WqWp[k,n]
    mma_gemm<<<ggw, 256, SMEMB, s1>>>(wp16, wqrm, nullptr, zeros, 0, nullptr,
                                      nullptr, nullptr, g16, nullptr, 0);
    cudaEventRecord(evG, s1);

    // main: Q path with fused q-logits
    cvt_kernel<<<(n4 + 255) / 256, 256>>>(x_q, xq16, n4);
    wcvt_kernel<<<wg, 256>>>(Wq, wq16);
    wqacvt_kernel<<<(128 * Cdim) / 256, 256>>>(Wqa, WqaT);
    mma_gemm<<<gg9, 256, SMEMB>>>(xq16, wq16, WqaT, bq, 0, bqa,
                                  nullptr, Qb, nullptr, lg, 0);
    cudaEventRecord(evQ, 0);

    // main: K GEMM
    cudaStreamWaitEvent(0, evCvt, 0);
    mma_gemm<<<gg8, 256, SMEMB>>>(xkv16, wk16, nullptr, bk, 0, nullptr,
                                  nullptr, Kb, nullptr, nullptr, 0);
    cudaEventRecord(evK, 0);

    // main: P1 = xq @ G  (overlaps s1 k-chain + Mb build)
    cudaStreamWaitEvent(0, evG, 0);
    mma_gemm<<<gg8, 256, SMEMB>>>(xq16, g16, nullptr, zeros, 0, nullptr,
                                  nullptr, out, nullptr, nullptr, 0);

    // s1: q-chain (overlaps K GEMM)
    cudaStreamWaitEvent(s1, evQ, 0);
    softmax_L_kernel<<<NB * Hn, 256, 0, s1>>>(lg, wb);
    pool_kernel<<<dim3(Hn, NB), 1024, 0, s1>>>(wb, Qb, pq);
    // s1: k-chain + Mb build (overlaps P1)
    cudaStreamWaitEvent(s1, evK, 0);
    attn_logits_kernel<<<Mrows / 8, 256, 0, s1>>>(Kb, Wka, bka, pq, lg);
    softmax_L_kernel<<<NB * Hn, 256, 0, s1>>>(lg, wb);
    pool_kernel<<<dim3(Hn, NB), 1024, 0, s1>>>(wb, Kb, pk);
    wtb_kernel<<<(NB * Cdim * (Cdim / 2)) / 256, 256, 0, s1>>>(pk, wtwp, Ab);
    // Mb[b][n][k] = (Wv diag(pk_b) WtWp)[k,n]
    mma_gemm<<<ggm, 256, SMEMB, s1>>>(Ab, wvrm, nullptr, zeros, 0, nullptr,
                                      nullptr, nullptr, Mb, nullptr, 0);
    cb_kernel<<<(NB * Cdim) / 8, 256, 0, s1>>>(pk, wtwp, wp16, bv, bt, bq, bp, cbv);
    cudaEventRecord(evJoin, s1);

    // ---- join: P2 = xkv @ Mb + cb_b + out ----
    cudaStreamWaitEvent(0, evJoin, 0);
    mma_gemm<<<gg8, 256, SMEMB>>>(xkv16, Mb, nullptr, cbv, 1, nullptr,
                                  out, out, nullptr, nullptr, WSZ);
}

// round 12
// speedup vs baseline: 2.1483x; 1.3750x over previous
#include <cuda_runtime.h>
#include <cuda_fp16.h>
#include <cstdint>

#define Cdim 1024
#define Hn   16
#define NB   8
#define Lseq 4096
#define Mrows (NB * Lseq)      // 32768
#define ATT_SCALE 0.125f

// ---------------------------------------------------------------------------
// Scratch
// ---------------------------------------------------------------------------
__device__ float g_logits[(size_t)Mrows * Hn];
__device__ float g_wbuf[(size_t)NB * Hn * Lseq];
__device__ float g_pq[NB * Cdim];
__device__ float g_pk[NB * Cdim];
__device__ float g_cb[NB * Cdim];
__device__ float g_zeros[Cdim];                       // stays zero
__device__ float g_pxp[(size_t)8 * NB * Hn * Cdim];   // lseg partials
__device__ float g_px[(size_t)NB * Hn * Cdim];
__device__ float g_blq[Hn];
__device__ float g_blk[NB * Hn];

__device__ __half g_xq16[(size_t)Mrows * Cdim];
__device__ __half g_xkv16[(size_t)Mrows * Cdim];
__device__ __half g_wp16[(size_t)Cdim * Cdim];        // K-major Wp
__device__ __half g_wqrm[(size_t)Cdim * Cdim];        // row-major fp16
__device__ __half g_wtrm[(size_t)Cdim * Cdim];
__device__ __half g_wvrm[(size_t)Cdim * Cdim];
__device__ __half g_wtwp[(size_t)Cdim * Cdim];        // (WtWp)^T
__device__ __half g_g16[(size_t)Cdim * Cdim];         // (WqWp)^T
__device__ __half g_Ab[(size_t)NB * Cdim * Cdim];
__device__ __half g_Mb[(size_t)NB * Cdim * Cdim];
__device__ __half g_wqwqa[(size_t)128 * Cdim];        // rows 0..15 = (WqWqa)^T
__device__ __half g_wkab[(size_t)NB * 128 * Cdim];    // per-batch gated

// ---------------------------------------------------------------------------
// PTX helpers
// ---------------------------------------------------------------------------
__device__ __forceinline__ uint32_t smem_u32(const void* p) {
    uint32_t a;
    asm("{ .reg .u64 t; cvta.to.shared.u64 t, %1; cvt.u32.u64 %0, t; }" : "=r"(a) : "l"(p));
    return a;
}
__device__ __forceinline__ void cpa16(uint32_t dst, const void* src) {
    asm volatile("cp.async.cg.shared.global [%0], [%1], 16;" :: "r"(dst), "l"(src) : "memory");
}
__device__ __forceinline__ void cpa_commit() {
    asm volatile("cp.async.commit_group;" ::: "memory");
}
__device__ __forceinline__ void cpa_wait1() {
    asm volatile("cp.async.wait_group 1;" ::: "memory");
}
__device__ __forceinline__ void ldm_x4(uint32_t* r, uint32_t addr) {
    asm volatile("ldmatrix.sync.aligned.m8n8.x4.shared.b16 {%0,%1,%2,%3}, [%4];"
                 : "=r"(r[0]), "=r"(r[1]), "=r"(r[2]), "=r"(r[3]) : "r"(addr));
}
__device__ __forceinline__ void mma_fp16(float* c, const uint32_t* a, const uint32_t* b) {
    asm volatile(
        "mma.sync.aligned.m16n8k16.row.col.f32.f16.f16.f32 "
        "{%0,%1,%2,%3}, {%4,%5,%6,%7}, {%8,%9}, {%0,%1,%2,%3};"
        : "+f"(c[0]), "+f"(c[1]), "+f"(c[2]), "+f"(c[3])
        : "r"(a[0]), "r"(a[1]), "r"(a[2]), "r"(a[3]), "r"(b[0]), "r"(b[1]));
}

// ---------------------------------------------------------------------------
// HMMA GEMM; slim mode = N=16 logits GEMM (B from Bw2, per-batch b2stride)
// ---------------------------------------------------------------------------
#define ROWB   144
#define TILEB  (128 * ROWB)
#define STAGEB (2 * TILEB)
#define STAGES 3
#define SMEMB  (STAGES * STAGEB)   // 110592

__device__ __forceinline__ void issue_stage(
    uint32_t sb, int s, int chunk, int tid,
    const __half* Aw, const __half* Bsrc, int grow0, int ncol0)
{
    uint32_t stb = sb + (uint32_t)s * STAGEB;
    int k0 = chunk * 64;
#pragma unroll
    for (int j = 0; j < 8; j++) {
        int id = tid + j * 256;
        int t4 = id >> 10;
        int w  = id & 1023;
        int r  = w >> 3, c = w & 7;
        const __half* src = (t4 == 0) ? Aw : Bsrc;
        int rb = (t4 == 0) ? grow0 : ncol0;
        const void* g = src + ((size_t)(rb + r) * Cdim + k0 + c * 8);
        cpa16(stb + (uint32_t)t4 * TILEB + (uint32_t)(r * ROWB + c * 16), g);
    }
}

__global__ void __launch_bounds__(256, 2) mma_gemm(
    const __half* __restrict__ Aw, const __half* __restrict__ Bw,
    const __half* __restrict__ Bw2,
    const float* __restrict__ bias, int bias_batched,
    const float* __restrict__ bias2, int bias2_batched,
    const float* __restrict__ addmat,
    float* __restrict__ outf, __half* __restrict__ out16,
    float* __restrict__ logits_out,
    size_t bstride, size_t b2stride, int slim)
{
    extern __shared__ char smem[];
    uint32_t sb = smem_u32(smem);
    int tid = threadIdx.x;
    int lane = tid & 31, wid = tid >> 5;
    int wm = wid & 1, wc = wid >> 1;
    int bM = blockIdx.y * 128, bN = blockIdx.x * 128;
    const __half* Bsrc;
    int ncol0;
    if (slim) { Bsrc = Bw2 + (size_t)(bM >> 12) * b2stride; ncol0 = 0; }
    else      { Bsrc = Bw + (size_t)(bM >> 12) * bstride; ncol0 = bN; }

    float acc[4][4][4];
#pragma unroll
    for (int i = 0; i < 4; i++)
#pragma unroll
        for (int j = 0; j < 4; j++)
#pragma unroll
            for (int q = 0; q < 4; q++) acc[i][j][q] = 0.f;

    int grp = lane >> 3, l7 = lane & 7;
    uint32_t a_off = (uint32_t)((l7 + ((grp & 1) << 3)) * ROWB + ((grp >> 1) << 4));
    uint32_t b_off = (uint32_t)((l7 + ((grp >> 1) << 3)) * ROWB + ((grp & 1) << 4));

#pragma unroll
    for (int s = 0; s < 2; s++) {
        issue_stage(sb, s, s, tid, Aw, Bsrc, bM, ncol0);
        cpa_commit();
    }

    for (int k = 0; k < 16; k++) {
        cpa_wait1();
        __syncthreads();
        if (k + 2 < 16)
            issue_stage(sb, (k + 2) % 3, k + 2, tid, Aw, Bsrc, bM, ncol0);
        cpa_commit();

        uint32_t st = sb + (uint32_t)(k % 3) * STAGEB;
        if (!slim) {
#pragma unroll
            for (int kk = 0; kk < 4; kk++) {
                uint32_t kb = (uint32_t)(kk * 32);
                uint32_t bh[8];
#pragma unroll
                for (int h = 0; h < 2; h++) {
                    uint32_t nrow = (uint32_t)((wc * 32 + h * 16) * ROWB);
                    ldm_x4(bh + h * 4, st + TILEB + nrow + b_off + kb);
                }
#pragma unroll
                for (int mt = 0; mt < 4; mt++) {
                    uint32_t mrow = (uint32_t)((wm * 64 + mt * 16) * ROWB);
                    uint32_t ah[4];
                    ldm_x4(ah, st + mrow + a_off + kb);
#pragma unroll
                    for (int nt = 0; nt < 4; nt++)
                        mma_fp16(acc[mt][nt], ah, &bh[nt * 2]);
                }
            }
        } else if (wc == 0) {   // slim: only first 16 cols matter
#pragma unroll
            for (int kk = 0; kk < 4; kk++) {
                uint32_t kb = (uint32_t)(kk * 32);
                uint32_t bh[4];
                ldm_x4(bh, st + TILEB + b_off + kb);
#pragma unroll
                for (int mt = 0; mt < 4; mt++) {
                    uint32_t mrow = (uint32_t)((wm * 64 + mt * 16) * ROWB);
                    uint32_t ah[4];
                    ldm_x4(ah, st + mrow + a_off + kb);
                    mma_fp16(acc[mt][0], ah, &bh[0]);
                    mma_fp16(acc[mt][1], ah, &bh[2]);
                }
            }
        }
    }

    // ---------------- epilogue ----------------
    int nidx = bM >> 12;
    if (slim) {
        if (wc == 0) {
            const float* b2 = bias2 + (bias2_batched ? (size_t)nidx * Hn : 0);
#pragma unroll
            for (int mt = 0; mt < 4; mt++) {
                int m0 = bM + wm * 64 + mt * 16 + (lane >> 2);
#pragma unroll
                for (int nt = 0; nt < 2; nt++) {
                    int h = nt * 8 + (lane & 3) * 2;
                    float b0 = b2[h], b1 = b2[h + 1];
                    float2 v0 = make_float2((acc[mt][nt][0] + b0) * ATT_SCALE,
                                            (acc[mt][nt][1] + b1) * ATT_SCALE);
                    float2 v1 = make_float2((acc[mt][nt][2] + b0) * ATT_SCALE,
                                            (acc[mt][nt][3] + b1) * ATT_SCALE);
                    *(float2*)(logits_out + (size_t)m0 * Hn + h) = v0;
                    *(float2*)(logits_out + (size_t)(m0 + 8) * Hn + h) = v1;
                }
            }
        }
        return;
    }

    const float* bptr = bias + (bias_batched ? (size_t)nidx * Cdim : 0);
#pragma unroll
    for (int mt = 0; mt < 4; mt++) {
        int m0 = bM + wm * 64 + mt * 16 + (lane >> 2);
#pragma unroll
        for (int nt = 0; nt < 4; nt++) {
            int n = bN + wc * 32 + nt * 8 + (lane & 3) * 2;
            float b0 = bptr[n], b1 = bptr[n + 1];
            float v0 = acc[mt][nt][0] + b0, v1 = acc[mt][nt][1] + b1;
            float v2 = acc[mt][nt][2] + b0, v3 = acc[mt][nt][3] + b1;
            size_t o0 = (size_t)m0 * Cdim + n;
            size_t o1 = (size_t)(m0 + 8) * Cdim + n;
            if (addmat) {
                float2 a0 = *(const float2*)(addmat + o0);
                float2 a1 = *(const float2*)(addmat + o1);
                v0 += a0.x; v1 += a0.y; v2 += a1.x; v3 += a1.y;
            }
            if (outf) {
                *(float2*)(outf + o0) = make_float2(v0, v1);
                *(float2*)(outf + o1) = make_float2(v2, v3);
            }
            if (out16) {
                *(__half2*)(out16 + o0) =
                    __halves2half2(__float2half(v0), __float2half(v1));
                *(__half2*)(out16 + o1) =
                    __halves2half2(__float2half(v2), __float2half(v3));
            }
        }
    }
}

// ---------------------------------------------------------------------------
// fp32 -> fp16 elementwise
// ---------------------------------------------------------------------------
__global__ __launch_bounds__(256) void cvt_kernel(
    const float* __restrict__ src, __half* __restrict__ dst, int n4)
{
    int i = blockIdx.x * 256 + threadIdx.x;
    if (i >= n4) return;
    float4 x = ((const float4*)src)[i];
    ((__half2*)dst)[2 * i]     = __halves2half2(__float2half(x.x), __float2half(x.y));
    ((__half2*)dst)[2 * i + 1] = __halves2half2(__float2half(x.z), __float2half(x.w));
}

// ---------------------------------------------------------------------------
// W[k][n] fp32 -> WT[n][k] fp16
// ---------------------------------------------------------------------------
__global__ __launch_bounds__(256) void wcvt_kernel(
    const float* __restrict__ W, __half* __restrict__ T16)
{
    __shared__ float t[32][33];
    int tx = threadIdx.x & 31, ty = threadIdx.x >> 5;
    int n0 = blockIdx.x * 32, k0 = blockIdx.y * 32;
#pragma unroll
    for (int i = 0; i < 32; i += 8)
        t[ty + i][tx] = W[(size_t)(k0 + ty + i) * Cdim + n0 + tx];
    __syncthreads();
#pragma unroll
    for (int i = 0; i < 32; i += 8) {
        size_t o = (size_t)(n0 + ty + i) * Cdim + k0 + tx;
        T16[o] = __float2half(t[tx][ty + i]);
    }
}

// ---------------------------------------------------------------------------
// wprod: out[(b*128+h)*C + j] = Σ_c Wleft[j,c]·(scale?scale[b,c]:1)·Wa[c,h]
// warp per (b,j). grid = nb*C/8 blocks of 256.
// ---------------------------------------------------------------------------
__global__ __launch_bounds__(256) void wprod_kernel(
    const float* __restrict__ Wleft, const float* __restrict__ Wa,
    const float* __restrict__ scale, __half* __restrict__ outw)
{
    int gw = blockIdx.x * 8 + (threadIdx.x >> 5);
    int lane = threadIdx.x & 31;
    int b = gw >> 10, j = gw & 1023;
    const float* wl = Wleft + (size_t)j * Cdim;
    const float* sv = scale ? scale + (size_t)b * Cdim : nullptr;

    float acc[16];
#pragma unroll
    for (int h = 0; h < 16; h++) acc[h] = 0.f;
    for (int c = lane; c < Cdim; c += 32) {
        float v = wl[c];
        if (sv) v *= sv[c];
        const float4* a4 = (const float4*)(Wa + (size_t)c * 16);
        float4 a0 = a4[0], a1 = a4[1], a2 = a4[2], a3 = a4[3];
        acc[0]  += v * a0.x; acc[1]  += v * a0.y; acc[2]  += v * a0.z; acc[3]  += v * a0.w;
        acc[4]  += v * a1.x; acc[5]  += v * a1.y; acc[6]  += v * a1.z; acc[7]  += v * a1.w;
        acc[8]  += v * a2.x; acc[9]  += v * a2.y; acc[10] += v * a2.z; acc[11] += v * a2.w;
        acc[12] += v * a3.x; acc[13] += v * a3.y; acc[14] += v * a3.z; acc[15] += v * a3.w;
    }
#pragma unroll
    for (int h = 0; h < 16; h++) {
        float v = acc[h];
#pragma unroll
        for (int o = 16; o; o >>= 1) v += __shfl_xor_sync(0xffffffffu, v, o);
        if (lane == h) outw[((size_t)(b * 128 + h)) * Cdim + j] = __float2half(v);
    }
}

// ---------------------------------------------------------------------------
// blvec: out[b*16+h] = Σ_c bvec[c]·(scale?scale[b,c]:1)·Wa[c,h] + badd[h]
// ---------------------------------------------------------------------------
__global__ __launch_bounds__(512) void blvec_kernel(
    const float* __restrict__ bvec, const float* __restrict__ scale,
    const float* __restrict__ Wa, const float* __restrict__ badd,
    float* __restrict__ outv)
{
    int b = blockIdx.x, h = threadIdx.x >> 5, lane = threadIdx.x & 31;
    float s = 0.f;
    for (int c = lane; c < Cdim; c += 32) {
        float v = bvec[c];
        if (scale) v *= scale[(size_t)b * Cdim + c];
        s += v * Wa[(size_t)c * 16 + h];
    }
#pragma unroll
    for (int o = 16; o; o >>= 1) s += __shfl_xor_sync(0xffffffffu, s, o);
    if (lane == 0) outv[b * 16 + h] = s + badd[h];
}

// ---------------------------------------------------------------------------
// poolx partials: pxp[(lseg*8+n)*16+h][c] = Σ_{l in seg} w[n,h,l]·x16[n,l,c]
// grid (8 lseg, 8 n, 4 cg), block 256
// ---------------------------------------------------------------------------
__global__ __launch_bounds__(256) void poolx_kernel(
    const float* __restrict__ w, const __half* __restrict__ x16,
    float* __restrict__ pxp)
{
    int lseg = blockIdx.x, n = blockIdx.y;
    int c = blockIdx.z * 256 + threadIdx.x;
    int tid = threadIdx.x;
    __shared__ float ws[16][128];

    float acc[16];
#pragma unroll
    for (int h = 0; h < 16; h++) acc[h] = 0.f;

    for (int chunk = 0; chunk < 4; chunk++) {
        int lb = lseg * 512 + chunk * 128;
#pragma unroll
        for (int i = 0; i < 8; i++) {
            int idx = tid + i * 256;
            ws[idx >> 7][idx & 127] =
                w[((size_t)n * Hn + (idx >> 7)) * Lseq + lb + (idx & 127)];
        }
        __syncthreads();
        for (int l = 0; l < 128; l++) {
            float a = __half2float(x16[((size_t)(n * Lseq + lb + l)) * Cdim + c]);
#pragma unroll
            for (int h = 0; h < 16; h++) acc[h] = fmaf(ws[h][l], a, acc[h]);
        }
        __syncthreads();
    }
#pragma unroll
    for (int h = 0; h < 16; h++)
        pxp[((size_t)((lseg * 8 + n) * 16 + h)) * Cdim + c] = acc[h];
}

__global__ __launch_bounds__(256) void poolx_reduce_kernel(
    const float* __restrict__ pxp, float* __restrict__ px)
{
    int idx = blockIdx.x * 256 + threadIdx.x;    // 0..131071
    int c = idx & 1023, hn = idx >> 10;          // hn = n*16+h
    float s = 0.f;
#pragma unroll
    for (int lseg = 0; lseg < 8; lseg++)
        s += pxp[((size_t)(lseg * 128 + hn)) * Cdim + c];
    px[idx] = s;
}

// ---------------------------------------------------------------------------
// pooled contraction: pooled[n, h*64+d] = Σ_j px[n,h,j]·Wx[j, h*64+d] + bvec[h*64+d]
// grid (16 h, 8 n), block 256
// ---------------------------------------------------------------------------
__global__ __launch_bounds__(256) void pcontract_kernel(
    const float* __restrict__ px, const float* __restrict__ Wx,
    const float* __restrict__ bvec, float* __restrict__ pooled)
{
    int h = blockIdx.x, n = blockIdx.y;
    int tid = threadIdx.x;
    int d = tid & 63, seg = tid >> 6;
    const float* pxr = px + ((size_t)n * Hn + h) * Cdim;
    float acc = 0.f;
    for (int j = seg * 256; j < seg * 256 + 256; j++)
        acc = fmaf(pxr[j], Wx[(size_t)j * Cdim + h * 64 + d], acc);
    __shared__ float red[256];
    red[tid] = acc;
    __syncthreads();
    if (tid < 64) {
        float s = red[tid] + red[tid + 64] + red[tid + 128] + red[tid + 192];
        pooled[(size_t)n * Cdim + h * 64 + tid] = s + bvec[h * 64 + tid];
    }
}

// ---------------------------------------------------------------------------
// softmax over L (unchanged)
// ---------------------------------------------------------------------------
__global__ __launch_bounds__(256) void softmax_L_kernel(
    const float* __restrict__ logits, float* __restrict__ w_out)
{
    int n = blockIdx.x / Hn, h = blockIdx.x % Hn;
    __shared__ float buf[Lseq];
    __shared__ float red[256];
    int tid = threadIdx.x;

    float m = -1e30f;
    for (int l = tid; l < Lseq; l += 256) {
        float v = logits[((size_t)n * Lseq + l) * Hn + h];
        buf[l] = v;
        m = fmaxf(m, v);
    }
    red[tid] = m; __syncthreads();
    for (int s = 128; s; s >>= 1) {
        if (tid < s) red[tid] = fmaxf(red[tid], red[tid + s]);
        __syncthreads();
    }
    m = red[0]; __syncthreads();

    float sum = 0.f;
    for (int l = tid; l < Lseq; l += 256) {
        float e = __expf(buf[l] - m);
        buf[l] = e;
        sum += e;
    }
    red[tid] = sum; __syncthreads();
    for (int s = 128; s; s >>= 1) {
        if (tid < s) red[tid] += red[tid + s];
        __syncthreads();
    }
    float inv = 1.f / red[0];

    float* wp = w_out + ((size_t)n * Hn + h) * Lseq;
    for (int l = tid; l < Lseq; l += 256) wp[l] = buf[l] * inv;
}

// ---------------------------------------------------------------------------
// wtb / cb (unchanged from R11)
// ---------------------------------------------------------------------------
__global__ __launch_bounds__(256) void wtb_kernel(
    const float* __restrict__ pk, const __half* __restrict__ src,
    __half* __restrict__ outw)
{
    size_t i = (size_t)blockIdx.x * 256 + threadIdx.x;
    int k2 = (int)(i & 511);
    int n  = (int)((i >> 9) & 1023);
    int b  = (int)(i >> 19);
    float2 wf = __half22float2(((const __half2*)src)[((size_t)n << 9) | k2]);
    float s0 = pk[b * Cdim + k2 * 2];
    float s1 = pk[b * Cdim + k2 * 2 + 1];
    ((__half2*)outw)[i] = __floats2half2_rn(wf.x * s0, wf.y * s1);
}

__global__ __launch_bounds__(256) void cb_kernel(
    const float* __restrict__ pk, const __half* __restrict__ wtwp,
    const __half* __restrict__ wp16,
    const float* __restrict__ bv, const float* __restrict__ bt,
    const float* __restrict__ bq, const float* __restrict__ bp,
    float* __restrict__ cb)
{
    int warp = threadIdx.x >> 5, lane = threadIdx.x & 31;
    int idx = blockIdx.x * 8 + warp;
    int b = idx >> 10, n = idx & 1023;
    float s = 0.f;
    for (int j = lane; j < Cdim; j += 32) {
        s += __half2float(wtwp[(size_t)n * Cdim + j]) * bv[j] * pk[b * Cdim + j];
        s += __half2float(wp16[(size_t)n * Cdim + j]) * (bt[j] + bq[j]);
    }
#pragma unroll
    for (int o = 16; o; o >>= 1) s += __shfl_xor_sync(0xffffffffu, s, o);
    if (lane == 0) cb[b * Cdim + n] = s + bp[n];
}

// ---------------------------------------------------------------------------
// Launch
// ---------------------------------------------------------------------------
extern "C" void kernel_launch(void* const* d_in, const int* in_sizes, int n_in,
                              void* d_out, int out_size)
{
    const float* x_q  = (const float*)d_in[0];
    const float* x_kv = (const float*)d_in[1];
    const float* Wq   = (const float*)d_in[2];
    const float* bq   = (const float*)d_in[3];
    const float* Wqa  = (const float*)d_in[4];
    const float* bqa  = (const float*)d_in[5];
    const float* Wk   = (const float*)d_in[6];
    const float* bk   = (const float*)d_in[7];
    const float* Wka  = (const float*)d_in[8];
    const float* bka  = (const float*)d_in[9];
    const float* Wv   = (const float*)d_in[10];
    const float* bv   = (const float*)d_in[11];
    const float* Wt   = (const float*)d_in[12];
    const float* bt   = (const float*)d_in[13];
    const float* Wp   = (const float*)d_in[14];
    const float* bp   = (const float*)d_in[15];
    float* out = (float*)d_out;

    float *lg, *wb, *pq, *pk, *cbv, *zeros, *pxp, *px, *blq, *blk;
    __half *xq16, *xkv16, *wp16, *wqrm, *wtrm, *wvrm, *wtwp, *g16, *Ab, *Mb;
    __half *wqwqa, *wkab;
    cudaGetSymbolAddress((void**)&lg, g_logits);
    cudaGetSymbolAddress((void**)&wb, g_wbuf);
    cudaGetSymbolAddress((void**)&pq, g_pq);
    cudaGetSymbolAddress((void**)&pk, g_pk);
    cudaGetSymbolAddress((void**)&cbv, g_cb);
    cudaGetSymbolAddress((void**)&zeros, g_zeros);
    cudaGetSymbolAddress((void**)&pxp, g_pxp);
    cudaGetSymbolAddress((void**)&px, g_px);
    cudaGetSymbolAddress((void**)&blq, g_blq);
    cudaGetSymbolAddress((void**)&blk, g_blk);
    cudaGetSymbolAddress((void**)&xq16, g_xq16);
    cudaGetSymbolAddress((void**)&xkv16, g_xkv16);
    cudaGetSymbolAddress((void**)&wp16, g_wp16);
    cudaGetSymbolAddress((void**)&wqrm, g_wqrm);
    cudaGetSymbolAddress((void**)&wtrm, g_wtrm);
    cudaGetSymbolAddress((void**)&wvrm, g_wvrm);
    cudaGetSymbolAddress((void**)&wtwp, g_wtwp);
    cudaGetSymbolAddress((void**)&g16, g_g16);
    cudaGetSymbolAddress((void**)&Ab, g_Ab);
    cudaGetSymbolAddress((void**)&Mb, g_Mb);
    cudaGetSymbolAddress((void**)&wqwqa, g_wqwqa);
    cudaGetSymbolAddress((void**)&wkab, g_wkab);

    const size_t WSZ = (size_t)Cdim * Cdim;
    cudaFuncSetAttribute(mma_gemm, cudaFuncAttributeMaxDynamicSharedMemorySize, SMEMB);

    cudaStream_t s1;
    cudaStreamCreateWithFlags(&s1, cudaStreamNonBlocking);
    cudaEvent_t evFork, evCvtXq, evCvtKv, evWtwp, evP1;
    cudaEventCreateWithFlags(&evFork,  cudaEventDisableTiming);
    cudaEventCreateWithFlags(&evCvtXq, cudaEventDisableTiming);
    cudaEventCreateWithFlags(&evCvtKv, cudaEventDisableTiming);
    cudaEventCreateWithFlags(&evWtwp,  cudaEventDisableTiming);
    cudaEventCreateWithFlags(&evP1,    cudaEventDisableTiming);

    int n4 = Mrows * Cdim / 4;
    int w4 = Cdim * Cdim / 4;
    dim3 wg(32, 32);
    dim3 gg8(8, Mrows / 128);
    dim3 ggs(1, Mrows / 128);    // slim logits GEMM
    dim3 ggw(8, 8);
    dim3 ggm(8, 64);
    dim3 ggpool(8, 8, 4);

    // ---- fork ----
    cudaEventRecord(evFork, 0);
    cudaStreamWaitEvent(s1, evFork, 0);

    // s1: kv convert + weight chain + P1
    cvt_kernel<<<(n4 + 255) / 256, 256, 0, s1>>>(x_kv, xkv16, n4);
    cudaEventRecord(evCvtKv, s1);
    wcvt_kernel<<<wg, 256, 0, s1>>>(Wp, wp16);
    cvt_kernel<<<(w4 + 255) / 256, 256, 0, s1>>>(Wt, wtrm, w4);
    cvt_kernel<<<(w4 + 255) / 256, 256, 0, s1>>>(Wq, wqrm, w4);
    cvt_kernel<<<(w4 + 255) / 256, 256, 0, s1>>>(Wv, wvrm, w4);
    mma_gemm<<<ggw, 256, SMEMB, s1>>>(wp16, wtrm, nullptr, zeros, 0, nullptr, 0,
                                      nullptr, nullptr, wtwp, nullptr, 0, 0, 0);
    cudaEventRecord(evWtwp, s1);
    mma_gemm<<<ggw, 256, SMEMB, s1>>>(wp16, wqrm, nullptr, zeros, 0, nullptr, 0,
                                      nullptr, nullptr, g16, nullptr, 0, 0, 0);
    cudaStreamWaitEvent(s1, evCvtXq, 0);
    // P1 = xq @ (WqWp)
    mma_gemm<<<gg8, 256, SMEMB, s1>>>(xq16, g16, nullptr, zeros, 0, nullptr, 0,
                                      nullptr, out, nullptr, nullptr, 0, 0, 0);
    cudaEventRecord(evP1, s1);

    // main: q logits chain
    wprod_kernel<<<128, 256>>>(Wq, Wqa, nullptr, wqwqa);   // (WqWqa)^T rows 0..15
    blvec_kernel<<<1, 512>>>(bq, nullptr, Wqa, bqa, blq);
    cvt_kernel<<<(n4 + 255) / 256, 256>>>(x_q, xq16, n4);
    cudaEventRecord(evCvtXq, 0);
    mma_gemm<<<ggs, 256, SMEMB>>>(xq16, nullptr, wqwqa, nullptr, 0, blq, 0,
                                  nullptr, nullptr, nullptr, lg, 0, 0, 1);
    softmax_L_kernel<<<NB * Hn, 256>>>(lg, wb);
    poolx_kernel<<<ggpool, 256>>>(wb, xq16, pxp);
    poolx_reduce_kernel<<<512, 256>>>(pxp, px);
    pcontract_kernel<<<dim3(Hn, NB), 256>>>(px, Wq, bq, pq);

    // main: k logits chain (gated by pq)
    wprod_kernel<<<1024, 256>>>(Wk, Wka, pq, wkab);
    blvec_kernel<<<NB, 512>>>(bk, pq, Wka, bka, blk);
    cudaStreamWaitEvent(0, evCvtKv, 0);
    mma_gemm<<<ggs, 256, SMEMB>>>(xkv16, nullptr, wkab, nullptr, 0, blk, 1,
                                  nullptr, nullptr, nullptr, lg, 0,
                                  (size_t)128 * Cdim, 1);
    softmax_L_kernel<<<NB * Hn, 256>>>(lg, wb);
    poolx_kernel<<<ggpool, 256>>>(wb, xkv16, pxp);
    poolx_reduce_kernel<<<512, 256>>>(pxp, px);
    pcontract_kernel<<<dim3(Hn, NB), 256>>>(px, Wk, bk, pk);

    // main: Mb + cb + final P2
    cudaStreamWaitEvent(0, evWtwp, 0);
    wtb_kernel<<<(NB * Cdim * (Cdim / 2)) / 256, 256>>>(pk, wtwp, Ab);
    mma_gemm<<<ggm, 256, SMEMB>>>(Ab, wvrm, nullptr, zeros, 0, nullptr, 0,
                                  nullptr, nullptr, Mb, nullptr, 0, 0, 0);
    cb_kernel<<<(NB * Cdim) / 8, 256>>>(pk, wtwp, wp16, bv, bt, bq, bp, cbv);
    cudaStreamWaitEvent(0, evP1, 0);
    // P2 = xkv @ Mb + cb + out
    mma_gemm<<<gg8, 256, SMEMB>>>(xkv16, Mb, nullptr, cbv, 1, nullptr, 0,
                                  out, out, nullptr, nullptr, WSZ, 0, 0);
}

// round 13
// speedup vs baseline: 2.3444x; 1.0913x over previous
#include <cuda_runtime.h>
#include <cuda_fp16.h>
#include <cstdint>

#define Cdim 1024
#define Hn   16
#define NB   8
#define Lseq 4096
#define Mrows (NB * Lseq)      // 32768
#define ATT_SCALE 0.125f

// ---------------------------------------------------------------------------
// Scratch
// ---------------------------------------------------------------------------
__device__ float g_logits[(size_t)Mrows * Hn];
__device__ float g_wbuf[(size_t)NB * Hn * Lseq];
__device__ float g_pq[NB * Cdim];
__device__ float g_pk[NB * Cdim];
__device__ float g_cb[NB * Cdim];
__device__ float g_zeros[Cdim];                       // stays zero
__device__ float g_pxp[(size_t)8 * NB * Hn * Cdim];   // lseg partials
__device__ float g_blq[Hn];
__device__ float g_blk[NB * Hn];

__device__ __half g_xq16[(size_t)Mrows * Cdim];
__device__ __half g_xkv16[(size_t)Mrows * Cdim];
__device__ __half g_P16[(size_t)Mrows * Cdim];        // P1 partial (fp16)
__device__ __half g_wp16[(size_t)Cdim * Cdim];        // K-major Wp
__device__ __half g_wqrm[(size_t)Cdim * Cdim];        // row-major fp16
__device__ __half g_wtrm[(size_t)Cdim * Cdim];
__device__ __half g_wvrm[(size_t)Cdim * Cdim];
__device__ __half g_wtwp[(size_t)Cdim * Cdim];        // (WtWp)^T
__device__ __half g_g16[(size_t)Cdim * Cdim];         // (WqWp)^T
__device__ __half g_Ab[(size_t)NB * Cdim * Cdim];
__device__ __half g_Mb[(size_t)NB * Cdim * Cdim];
__device__ __half g_wqwqa[(size_t)128 * Cdim];        // rows 0..15 = (WqWqa)^T
__device__ __half g_wkab[(size_t)NB * 128 * Cdim];    // per-batch gated

// ---------------------------------------------------------------------------
// PTX helpers
// ---------------------------------------------------------------------------
__device__ __forceinline__ uint32_t smem_u32(const void* p) {
    uint32_t a;
    asm("{ .reg .u64 t; cvta.to.shared.u64 t, %1; cvt.u32.u64 %0, t; }" : "=r"(a) : "l"(p));
    return a;
}
__device__ __forceinline__ void cpa16(uint32_t dst, const void* src) {
    asm volatile("cp.async.cg.shared.global [%0], [%1], 16;" :: "r"(dst), "l"(src) : "memory");
}
__device__ __forceinline__ void cpa_commit() {
    asm volatile("cp.async.commit_group;" ::: "memory");
}
__device__ __forceinline__ void cpa_wait1() {
    asm volatile("cp.async.wait_group 1;" ::: "memory");
}
__device__ __forceinline__ void ldm_x4(uint32_t* r, uint32_t addr) {
    asm volatile("ldmatrix.sync.aligned.m8n8.x4.shared.b16 {%0,%1,%2,%3}, [%4];"
                 : "=r"(r[0]), "=r"(r[1]), "=r"(r[2]), "=r"(r[3]) : "r"(addr));
}
__device__ __forceinline__ void mma_fp16(float* c, const uint32_t* a, const uint32_t* b) {
    asm volatile(
        "mma.sync.aligned.m16n8k16.row.col.f32.f16.f16.f32 "
        "{%0,%1,%2,%3}, {%4,%5,%6,%7}, {%8,%9}, {%0,%1,%2,%3};"
        : "+f"(c[0]), "+f"(c[1]), "+f"(c[2]), "+f"(c[3])
        : "r"(a[0]), "r"(a[1]), "r"(a[2]), "r"(a[3]), "r"(b[0]), "r"(b[1]));
}

// ---------------------------------------------------------------------------
// HMMA GEMM; slim mode = N=16 logits GEMM (B from Bw2, per-batch b2stride)
// ---------------------------------------------------------------------------
#define ROWB   144
#define TILEB  (128 * ROWB)
#define STAGEB (2 * TILEB)
#define STAGES 3
#define SMEMB  (STAGES * STAGEB)   // 110592

__device__ __forceinline__ void issue_stage(
    uint32_t sb, int s, int chunk, int tid,
    const __half* Aw, const __half* Bsrc, int grow0, int ncol0, int slim)
{
    uint32_t stb = sb + (uint32_t)s * STAGEB;
    int k0 = chunk * 64;
#pragma unroll
    for (int j = 0; j < 8; j++) {
        int id = tid + j * 256;
        int t4 = id >> 10;
        int w  = id & 1023;
        int r  = w >> 3, c = w & 7;
        if (slim && t4 == 1 && r >= 16) continue;   // only 16 B-rows needed
        const __half* src = (t4 == 0) ? Aw : Bsrc;
        int rb = (t4 == 0) ? grow0 : ncol0;
        const void* g = src + ((size_t)(rb + r) * Cdim + k0 + c * 8);
        cpa16(stb + (uint32_t)t4 * TILEB + (uint32_t)(r * ROWB + c * 16), g);
    }
}

__global__ void __launch_bounds__(256, 2) mma_gemm(
    const __half* __restrict__ Aw, const __half* __restrict__ Bw,
    const __half* __restrict__ Bw2,
    const float* __restrict__ bias, int bias_batched,
    const float* __restrict__ bias2, int bias2_batched,
    const __half* __restrict__ addmat16,
    float* __restrict__ outf, __half* __restrict__ out16,
    float* __restrict__ logits_out,
    size_t bstride, size_t b2stride, int slim)
{
    extern __shared__ char smem[];
    uint32_t sb = smem_u32(smem);
    int tid = threadIdx.x;
    int lane = tid & 31, wid = tid >> 5;
    int wm = wid & 1, wc = wid >> 1;
    int bM = blockIdx.y * 128, bN = blockIdx.x * 128;
    const __half* Bsrc;
    int ncol0;
    if (slim) { Bsrc = Bw2 + (size_t)(bM >> 12) * b2stride; ncol0 = 0; }
    else      { Bsrc = Bw + (size_t)(bM >> 12) * bstride; ncol0 = bN; }

    float acc[4][4][4];
#pragma unroll
    for (int i = 0; i < 4; i++)
#pragma unroll
        for (int j = 0; j < 4; j++)
#pragma unroll
            for (int q = 0; q < 4; q++) acc[i][j][q] = 0.f;

    int grp = lane >> 3, l7 = lane & 7;
    uint32_t a_off = (uint32_t)((l7 + ((grp & 1) << 3)) * ROWB + ((grp >> 1) << 4));
    uint32_t b_off = (uint32_t)((l7 + ((grp >> 1) << 3)) * ROWB + ((grp & 1) << 4));

#pragma unroll
    for (int s = 0; s < 2; s++) {
        issue_stage(sb, s, s, tid, Aw, Bsrc, bM, ncol0, slim);
        cpa_commit();
    }

    for (int k = 0; k < 16; k++) {
        cpa_wait1();
        __syncthreads();
        if (k + 2 < 16)
            issue_stage(sb, (k + 2) % 3, k + 2, tid, Aw, Bsrc, bM, ncol0, slim);
        cpa_commit();

        uint32_t st = sb + (uint32_t)(k % 3) * STAGEB;
        if (!slim) {
#pragma unroll
            for (int kk = 0; kk < 4; kk++) {
                uint32_t kb = (uint32_t)(kk * 32);
                uint32_t bh[8];
#pragma unroll
                for (int h = 0; h < 2; h++) {
                    uint32_t nrow = (uint32_t)((wc * 32 + h * 16) * ROWB);
                    ldm_x4(bh + h * 4, st + TILEB + nrow + b_off + kb);
                }
#pragma unroll
                for (int mt = 0; mt < 4; mt++) {
                    uint32_t mrow = (uint32_t)((wm * 64 + mt * 16) * ROWB);
                    uint32_t ah[4];
                    ldm_x4(ah, st + mrow + a_off + kb);
#pragma unroll
                    for (int nt = 0; nt < 4; nt++)
                        mma_fp16(acc[mt][nt], ah, &bh[nt * 2]);
                }
            }
        } else if (wc == 0) {
#pragma unroll
            for (int kk = 0; kk < 4; kk++) {
                uint32_t kb = (uint32_t)(kk * 32);
                uint32_t bh[4];
                ldm_x4(bh, st + TILEB + b_off + kb);
#pragma unroll
                for (int mt = 0; mt < 4; mt++) {
                    uint32_t mrow = (uint32_t)((wm * 64 + mt * 16) * ROWB);
                    uint32_t ah[4];
                    ldm_x4(ah, st + mrow + a_off + kb);
                    mma_fp16(acc[mt][0], ah, &bh[0]);
                    mma_fp16(acc[mt][1], ah, &bh[2]);
                }
            }
        }
    }

    // ---------------- epilogue ----------------
    int nidx = bM >> 12;
    if (slim) {
        if (wc == 0) {
            const float* b2 = bias2 + (bias2_batched ? (size_t)nidx * Hn : 0);
#pragma unroll
            for (int mt = 0; mt < 4; mt++) {
                int m0 = bM + wm * 64 + mt * 16 + (lane >> 2);
#pragma unroll
                for (int nt = 0; nt < 2; nt++) {
                    int h = nt * 8 + (lane & 3) * 2;
                    float b0 = b2[h], b1 = b2[h + 1];
                    float2 v0 = make_float2((acc[mt][nt][0] + b0) * ATT_SCALE,
                                            (acc[mt][nt][1] + b1) * ATT_SCALE);
                    float2 v1 = make_float2((acc[mt][nt][2] + b0) * ATT_SCALE,
                                            (acc[mt][nt][3] + b1) * ATT_SCALE);
                    *(float2*)(logits_out + (size_t)m0 * Hn + h) = v0;
                    *(float2*)(logits_out + (size_t)(m0 + 8) * Hn + h) = v1;
                }
            }
        }
        return;
    }

    const float* bptr = bias + (bias_batched ? (size_t)nidx * Cdim : 0);
#pragma unroll
    for (int mt = 0; mt < 4; mt++) {
        int m0 = bM + wm * 64 + mt * 16 + (lane >> 2);
#pragma unroll
        for (int nt = 0; nt < 4; nt++) {
            int n = bN + wc * 32 + nt * 8 + (lane & 3) * 2;
            float b0 = bptr[n], b1 = bptr[n + 1];
            float v0 = acc[mt][nt][0] + b0, v1 = acc[mt][nt][1] + b1;
            float v2 = acc[mt][nt][2] + b0, v3 = acc[mt][nt][3] + b1;
            size_t o0 = (size_t)m0 * Cdim + n;
            size_t o1 = (size_t)(m0 + 8) * Cdim + n;
            if (addmat16) {
                float2 a0 = __half22float2(*(const __half2*)(addmat16 + o0));
                float2 a1 = __half22float2(*(const __half2*)(addmat16 + o1));
                v0 += a0.x; v1 += a0.y; v2 += a1.x; v3 += a1.y;
            }
            if (outf) {
                *(float2*)(outf + o0) = make_float2(v0, v1);
                *(float2*)(outf + o1) = make_float2(v2, v3);
            }
            if (out16) {
                *(__half2*)(out16 + o0) =
                    __halves2half2(__float2half(v0), __float2half(v1));
                *(__half2*)(out16 + o1) =
                    __halves2half2(__float2half(v2), __float2half(v3));
            }
        }
    }
}

// ---------------------------------------------------------------------------
// fp32 -> fp16 elementwise
// ---------------------------------------------------------------------------
__global__ __launch_bounds__(256) void cvt_kernel(
    const float* __restrict__ src, __half* __restrict__ dst, int n4)
{
    int i = blockIdx.x * 256 + threadIdx.x;
    if (i >= n4) return;
    float4 x = ((const float4*)src)[i];
    ((__half2*)dst)[2 * i]     = __halves2half2(__float2half(x.x), __float2half(x.y));
    ((__half2*)dst)[2 * i + 1] = __halves2half2(__float2half(x.z), __float2half(x.w));
}

// ---------------------------------------------------------------------------
// W[k][n] fp32 -> WT[n][k] fp16
// ---------------------------------------------------------------------------
__global__ __launch_bounds__(256) void wcvt_kernel(
    const float* __restrict__ W, __half* __restrict__ T16)
{
    __shared__ float t[32][33];
    int tx = threadIdx.x & 31, ty = threadIdx.x >> 5;
    int n0 = blockIdx.x * 32, k0 = blockIdx.y * 32;
#pragma unroll
    for (int i = 0; i < 32; i += 8)
        t[ty + i][tx] = W[(size_t)(k0 + ty + i) * Cdim + n0 + tx];
    __syncthreads();
#pragma unroll
    for (int i = 0; i < 32; i += 8) {
        size_t o = (size_t)(n0 + ty + i) * Cdim + k0 + tx;
        T16[o] = __float2half(t[tx][ty + i]);
    }
}

// ---------------------------------------------------------------------------
// wprod: out[(b*128+h)*C + j] = Σ_c Wleft[j,c]·(scale?scale[b,c]:1)·Wa[c,h]
// ---------------------------------------------------------------------------
__global__ __launch_bounds__(256) void wprod_kernel(
    const float* __restrict__ Wleft, const float* __restrict__ Wa,
    const float* __restrict__ scale, __half* __restrict__ outw)
{
    int gw = blockIdx.x * 8 + (threadIdx.x >> 5);
    int lane = threadIdx.x & 31;
    int b = gw >> 10, j = gw & 1023;
    const float* wl = Wleft + (size_t)j * Cdim;
    const float* sv = scale ? scale + (size_t)b * Cdim : nullptr;

    float acc[16];
#pragma unroll
    for (int h = 0; h < 16; h++) acc[h] = 0.f;
    for (int c = lane; c < Cdim; c += 32) {
        float v = wl[c];
        if (sv) v *= sv[c];
        const float4* a4 = (const float4*)(Wa + (size_t)c * 16);
        float4 a0 = a4[0], a1 = a4[1], a2 = a4[2], a3 = a4[3];
        acc[0]  += v * a0.x; acc[1]  += v * a0.y; acc[2]  += v * a0.z; acc[3]  += v * a0.w;
        acc[4]  += v * a1.x; acc[5]  += v * a1.y; acc[6]  += v * a1.z; acc[7]  += v * a1.w;
        acc[8]  += v * a2.x; acc[9]  += v * a2.y; acc[10] += v * a2.z; acc[11] += v * a2.w;
        acc[12] += v * a3.x; acc[13] += v * a3.y; acc[14] += v * a3.z; acc[15] += v * a3.w;
    }
#pragma unroll
    for (int h = 0; h < 16; h++) {
        float v = acc[h];
#pragma unroll
        for (int o = 16; o; o >>= 1) v += __shfl_xor_sync(0xffffffffu, v, o);
        if (lane == h) outw[((size_t)(b * 128 + h)) * Cdim + j] = __float2half(v);
    }
}

// ---------------------------------------------------------------------------
// blvec: out[b*16+h] = Σ_c bvec[c]·(scale?scale[b,c]:1)·Wa[c,h] + badd[h]
// ---------------------------------------------------------------------------
__global__ __launch_bounds__(512) void blvec_kernel(
    const float* __restrict__ bvec, const float* __restrict__ scale,
    const float* __restrict__ Wa, const float* __restrict__ badd,
    float* __restrict__ outv)
{
    int b = blockIdx.x, h = threadIdx.x >> 5, lane = threadIdx.x & 31;
    float s = 0.f;
    for (int c = lane; c < Cdim; c += 32) {
        float v = bvec[c];
        if (scale) v *= scale[(size_t)b * Cdim + c];
        s += v * Wa[(size_t)c * 16 + h];
    }
#pragma unroll
    for (int o = 16; o; o >>= 1) s += __shfl_xor_sync(0xffffffffu, s, o);
    if (lane == 0) outv[b * 16 + h] = s + badd[h];
}

// ---------------------------------------------------------------------------
// poolx partials
// ---------------------------------------------------------------------------
__global__ __launch_bounds__(256) void poolx_kernel(
    const float* __restrict__ w, const __half* __restrict__ x16,
    float* __restrict__ pxp)
{
    int lseg = blockIdx.x, n = blockIdx.y;
    int c = blockIdx.z * 256 + threadIdx.x;
    int tid = threadIdx.x;
    __shared__ float ws[16][128];

    float acc[16];
#pragma unroll
    for (int h = 0; h < 16; h++) acc[h] = 0.f;

    for (int chunk = 0; chunk < 4; chunk++) {
        int lb = lseg * 512 + chunk * 128;
#pragma unroll
        for (int i = 0; i < 8; i++) {
            int idx = tid + i * 256;
            ws[idx >> 7][idx & 127] =
                w[((size_t)n * Hn + (idx >> 7)) * Lseq + lb + (idx & 127)];
        }
        __syncthreads();
        for (int l = 0; l < 128; l++) {
            float a = __half2float(x16[((size_t)(n * Lseq + lb + l)) * Cdim + c]);
#pragma unroll
            for (int h = 0; h < 16; h++) acc[h] = fmaf(ws[h][l], a, acc[h]);
        }
        __syncthreads();
    }
#pragma unroll
    for (int h = 0; h < 16; h++)
        pxp[((size_t)((lseg * 8 + n) * 16 + h)) * Cdim + c] = acc[h];
}

// ---------------------------------------------------------------------------
// pcontract (fused lseg reduce): pooled[n, h*64+d] =
//   Σ_j (Σ_ls pxp[ls,n,h,j]) · Wx[j, h*64+d] + bvec[h*64+d]
// ---------------------------------------------------------------------------
__global__ __launch_bounds__(256) void pcontract_kernel(
    const float* __restrict__ pxp, const float* __restrict__ Wx,
    const float* __restrict__ bvec, float* __restrict__ pooled)
{
    int h = blockIdx.x, n = blockIdx.y;
    int tid = threadIdx.x;
    int d = tid & 63, seg = tid >> 6;
    int hn = n * Hn + h;
    __shared__ float ps[Cdim];
    // stage reduced px row into smem
    for (int j = tid; j < Cdim; j += 256) {
        float s = 0.f;
#pragma unroll
        for (int ls = 0; ls < 8; ls++)
            s += pxp[((size_t)(ls * 128 + hn)) * Cdim + j];
        ps[j] = s;
    }
    __syncthreads();
    float acc = 0.f;
    for (int j = seg * 256; j < seg * 256 + 256; j++)
        acc = fmaf(ps[j], Wx[(size_t)j * Cdim + h * 64 + d], acc);
    __shared__ float red[256];
    red[tid] = acc;
    __syncthreads();
    if (tid < 64) {
        float s = red[tid] + red[tid + 64] + red[tid + 128] + red[tid + 192];
        pooled[(size_t)n * Cdim + h * 64 + tid] = s + bvec[h * 64 + tid];
    }
}

// ---------------------------------------------------------------------------
// softmax over L
// ---------------------------------------------------------------------------
__global__ __launch_bounds__(256) void softmax_L_kernel(
    const float* __restrict__ logits, float* __restrict__ w_out)
{
    int n = blockIdx.x / Hn, h = blockIdx.x % Hn;
    __shared__ float buf[Lseq];
    __shared__ float red[256];
    int tid = threadIdx.x;

    float m = -1e30f;
    for (int l = tid; l < Lseq; l += 256) {
        float v = logits[((size_t)n * Lseq + l) * Hn + h];
        buf[l] = v;
        m = fmaxf(m, v);
    }
    red[tid] = m; __syncthreads();
    for (int s = 128; s; s >>= 1) {
        if (tid < s) red[tid] = fmaxf(red[tid], red[tid + s]);
        __syncthreads();
    }
    m = red[0]; __syncthreads();

    float sum = 0.f;
    for (int l = tid; l < Lseq; l += 256) {
        float e = __expf(buf[l] - m);
        buf[l] = e;
        sum += e;
    }
    red[tid] = sum; __syncthreads();
    for (int s = 128; s; s >>= 1) {
        if (tid < s) red[tid] += red[tid + s];
        __syncthreads();
    }
    float inv = 1.f / red[0];

    float* wp = w_out + ((size_t)n * Hn + h) * Lseq;
    for (int l = tid; l < Lseq; l += 256) wp[l] = buf[l] * inv;
}

// ---------------------------------------------------------------------------
// wtb / cb
// ---------------------------------------------------------------------------
__global__ __launch_bounds__(256) void wtb_kernel(
    const float* __restrict__ pk, const __half* __restrict__ src,
    __half* __restrict__ outw)
{
    size_t i = (size_t)blockIdx.x * 256 + threadIdx.x;
    int k2 = (int)(i & 511);
    int n  = (int)((i >> 9) & 1023);
    int b  = (int)(i >> 19);
    float2 wf = __half22float2(((const __half2*)src)[((size_t)n << 9) | k2]);
    float s0 = pk[b * Cdim + k2 * 2];
    float s1 = pk[b * Cdim + k2 * 2 + 1];
    ((__half2*)outw)[i] = __floats2half2_rn(wf.x * s0, wf.y * s1);
}

__global__ __launch_bounds__(256) void cb_kernel(
    const float* __restrict__ pk, const __half* __restrict__ wtwp,
    const __half* __restrict__ wp16,
    const float* __restrict__ bv, const float* __restrict__ bt,
    const float* __restrict__ bq, const float* __restrict__ bp,
    float* __restrict__ cb)
{
    int warp = threadIdx.x >> 5, lane = threadIdx.x & 31;
    int idx = blockIdx.x * 8 + warp;
    int b = idx >> 10, n = idx & 1023;
    float s = 0.f;
    for (int j = lane; j < Cdim; j += 32) {
        s += __half2float(wtwp[(size_t)n * Cdim + j]) * bv[j] * pk[b * Cdim + j];
        s += __half2float(wp16[(size_t)n * Cdim + j]) * (bt[j] + bq[j]);
    }
#pragma unroll
    for (int o = 16; o; o >>= 1) s += __shfl_xor_sync(0xffffffffu, s, o);
    if (lane == 0) cb[b * Cdim + n] = s + bp[n];
}

// ---------------------------------------------------------------------------
// Launch
// ---------------------------------------------------------------------------
extern "C" void kernel_launch(void* const* d_in, const int* in_sizes, int n_in,
                              void* d_out, int out_size)
{
    const float* x_q  = (const float*)d_in[0];
    const float* x_kv = (const float*)d_in[1];
    const float* Wq   = (const float*)d_in[2];
    const float* bq   = (const float*)d_in[3];
    const float* Wqa  = (const float*)d_in[4];
    const float* bqa  = (const float*)d_in[5];
    const float* Wk   = (const float*)d_in[6];
    const float* bk   = (const float*)d_in[7];
    const float* Wka  = (const float*)d_in[8];
    const float* bka  = (const float*)d_in[9];
    const float* Wv   = (const float*)d_in[10];
    const float* bv   = (const float*)d_in[11];
    const float* Wt   = (const float*)d_in[12];
    const float* bt   = (const float*)d_in[13];
    const float* Wp   = (const float*)d_in[14];
    const float* bp   = (const float*)d_in[15];
    float* out = (float*)d_out;

    float *lg, *wb, *pq, *pk, *cbv, *zeros, *pxp, *blq, *blk;
    __half *xq16, *xkv16, *P16, *wp16, *wqrm, *wtrm, *wvrm, *wtwp, *g16;
    __half *Ab, *Mb, *wqwqa, *wkab;
    cudaGetSymbolAddress((void**)&lg, g_logits);
    cudaGetSymbolAddress((void**)&wb, g_wbuf);
    cudaGetSymbolAddress((void**)&pq, g_pq);
    cudaGetSymbolAddress((void**)&pk, g_pk);
    cudaGetSymbolAddress((void**)&cbv, g_cb);
    cudaGetSymbolAddress((void**)&zeros, g_zeros);
    cudaGetSymbolAddress((void**)&pxp, g_pxp);
    cudaGetSymbolAddress((void**)&blq, g_blq);
    cudaGetSymbolAddress((void**)&blk, g_blk);
    cudaGetSymbolAddress((void**)&xq16, g_xq16);
    cudaGetSymbolAddress((void**)&xkv16, g_xkv16);
    cudaGetSymbolAddress((void**)&P16, g_P16);
    cudaGetSymbolAddress((void**)&wp16, g_wp16);
    cudaGetSymbolAddress((void**)&wqrm, g_wqrm);
    cudaGetSymbolAddress((void**)&wtrm, g_wtrm);
    cudaGetSymbolAddress((void**)&wvrm, g_wvrm);
    cudaGetSymbolAddress((void**)&wtwp, g_wtwp);
    cudaGetSymbolAddress((void**)&g16, g_g16);
    cudaGetSymbolAddress((void**)&Ab, g_Ab);
    cudaGetSymbolAddress((void**)&Mb, g_Mb);
    cudaGetSymbolAddress((void**)&wqwqa, g_wqwqa);
    cudaGetSymbolAddress((void**)&wkab, g_wkab);

    const size_t WSZ = (size_t)Cdim * Cdim;
    cudaFuncSetAttribute(mma_gemm, cudaFuncAttributeMaxDynamicSharedMemorySize, SMEMB);

    cudaStream_t s1;
    cudaStreamCreateWithFlags(&s1, cudaStreamNonBlocking);
    cudaEvent_t evFork, evWq, evCvtXq, evCvtKv, evWtwp, evPk, evCb, evP1;
    cudaEventCreateWithFlags(&evFork,  cudaEventDisableTiming);
    cudaEventCreateWithFlags(&evWq,    cudaEventDisableTiming);
    cudaEventCreateWithFlags(&evCvtXq, cudaEventDisableTiming);
    cudaEventCreateWithFlags(&evCvtKv, cudaEventDisableTiming);
    cudaEventCreateWithFlags(&evWtwp,  cudaEventDisableTiming);
    cudaEventCreateWithFlags(&evPk,    cudaEventDisableTiming);
    cudaEventCreateWithFlags(&evCb,    cudaEventDisableTiming);
    cudaEventCreateWithFlags(&evP1,    cudaEventDisableTiming);

    int n4 = Mrows * Cdim / 4;
    int w4 = Cdim * Cdim / 4;
    dim3 wg(32, 32);
    dim3 gg8(8, Mrows / 128);
    dim3 ggs(1, Mrows / 128);
    dim3 ggw(8, 8);
    dim3 ggm(8, 64);
    dim3 ggpool(8, 8, 4);

    // ---- fork ----
    cudaEventRecord(evFork, 0);
    cudaStreamWaitEvent(s1, evFork, 0);

    // s1: q logit weights, kv convert, weight chain, P1
    wprod_kernel<<<128, 256, 0, s1>>>(Wq, Wqa, nullptr, wqwqa);
    blvec_kernel<<<1, 512, 0, s1>>>(bq, nullptr, Wqa, bqa, blq);
    cudaEventRecord(evWq, s1);
    cvt_kernel<<<(n4 + 255) / 256, 256, 0, s1>>>(x_kv, xkv16, n4);
    cudaEventRecord(evCvtKv, s1);
    wcvt_kernel<<<wg, 256, 0, s1>>>(Wp, wp16);
    cvt_kernel<<<(w4 + 255) / 256, 256, 0, s1>>>(Wt, wtrm, w4);
    cvt_kernel<<<(w4 + 255) / 256, 256, 0, s1>>>(Wq, wqrm, w4);
    cvt_kernel<<<(w4 + 255) / 256, 256, 0, s1>>>(Wv, wvrm, w4);
    mma_gemm<<<ggw, 256, SMEMB, s1>>>(wp16, wtrm, nullptr, zeros, 0, nullptr, 0,
                                      nullptr, nullptr, wtwp, nullptr, 0, 0, 0);
    cudaEventRecord(evWtwp, s1);
    mma_gemm<<<ggw, 256, SMEMB, s1>>>(wp16, wqrm, nullptr, zeros, 0, nullptr, 0,
                                      nullptr, nullptr, g16, nullptr, 0, 0, 0);
    cudaStreamWaitEvent(s1, evCvtXq, 0);
    // P1 = xq @ (WqWp)  -> fp16 temp
    mma_gemm<<<gg8, 256, SMEMB, s1>>>(xq16, g16, nullptr, zeros, 0, nullptr, 0,
                                      nullptr, nullptr, P16, nullptr, 0, 0, 0);
    cudaEventRecord(evP1, s1);
    // s1: cb (parallel with main's Mb GEMM)
    cudaStreamWaitEvent(s1, evPk, 0);
    cb_kernel<<<(NB * Cdim) / 8, 256, 0, s1>>>(pk, wtwp, wp16, bv, bt, bq, bp, cbv);
    cudaEventRecord(evCb, s1);

    // main: q logits chain
    cvt_kernel<<<(n4 + 255) / 256, 256>>>(x_q, xq16, n4);
    cudaEventRecord(evCvtXq, 0);
    cudaStreamWaitEvent(0, evWq, 0);
    mma_gemm<<<ggs, 256, SMEMB>>>(xq16, nullptr, wqwqa, nullptr, 0, blq, 0,
                                  nullptr, nullptr, nullptr, lg, 0, 0, 1);
    softmax_L_kernel<<<NB * Hn, 256>>>(lg, wb);
    poolx_kernel<<<ggpool, 256>>>(wb, xq16, pxp);
    pcontract_kernel<<<dim3(Hn, NB), 256>>>(pxp, Wq, bq, pq);

    // main: k logits chain (gated by pq)
    wprod_kernel<<<1024, 256>>>(Wk, Wka, pq, wkab);
    blvec_kernel<<<NB, 512>>>(bk, pq, Wka, bka, blk);
    cudaStreamWaitEvent(0, evCvtKv, 0);
    mma_gemm<<<ggs, 256, SMEMB>>>(xkv16, nullptr, wkab, nullptr, 0, blk, 1,
                                  nullptr, nullptr, nullptr, lg, 0,
                                  (size_t)128 * Cdim, 1);
    softmax_L_kernel<<<NB * Hn, 256>>>(lg, wb);
    poolx_kernel<<<ggpool, 256>>>(wb, xkv16, pxp);
    pcontract_kernel<<<dim3(Hn, NB), 256>>>(pxp, Wk, bk, pk);
    cudaEventRecord(evPk, 0);

    // main: Mb + final P2
    cudaStreamWaitEvent(0, evWtwp, 0);
    wtb_kernel<<<(NB * Cdim * (Cdim / 2)) / 256, 256>>>(pk, wtwp, Ab);
    mma_gemm<<<ggm, 256, SMEMB>>>(Ab, wvrm, nullptr, zeros, 0, nullptr, 0,
                                  nullptr, nullptr, Mb, nullptr, 0, 0, 0);
    cudaStreamWaitEvent(0, evCb, 0);
    cudaStreamWaitEvent(0, evP1, 0);
    // P2 = xkv @ Mb + cb + P16
    mma_gemm<<<gg8, 256, SMEMB>>>(xkv16, Mb, nullptr, cbv, 1, nullptr, 0,
                                  P16, out, nullptr, nullptr, WSZ, 0, 0);
}

// round 16
// speedup vs baseline: 2.3733x; 1.0123x over previous
#include <cuda_runtime.h>
#include <cuda_fp16.h>
#include <cstdint>

#define Cdim 1024
#define Hn   16
#define NB   8
#define Lseq 4096
#define Mrows (NB * Lseq)      // 32768
#define ATT_SCALE 0.125f

// ---------------------------------------------------------------------------
// Scratch
// ---------------------------------------------------------------------------
__device__ float g_logits[(size_t)Mrows * Hn];
__device__ float g_wbuf[(size_t)NB * Hn * Lseq];
__device__ float g_pq[NB * Cdim];
__device__ float g_pk[NB * Cdim];
__device__ float g_cb[NB * Cdim];
__device__ float g_zeros[Cdim];                        // stays zero
__device__ float g_pxp[(size_t)16 * NB * Hn * Cdim];   // lseg partials (16 segs)
__device__ float g_blq[Hn];
__device__ float g_blk[NB * Hn];

__device__ __half g_xq16[(size_t)Mrows * Cdim];
__device__ __half g_xkv16[(size_t)Mrows * Cdim];
__device__ __half g_P16[(size_t)Mrows * Cdim];        // P1 partial (fp16)
__device__ __half g_wp16[(size_t)Cdim * Cdim];        // K-major Wp
__device__ __half g_wqrm[(size_t)Cdim * Cdim];        // row-major fp16
__device__ __half g_wtrm[(size_t)Cdim * Cdim];
__device__ __half g_wvrm[(size_t)Cdim * Cdim];
__device__ __half g_wtwp[(size_t)Cdim * Cdim];        // (WtWp)^T
__device__ __half g_g16[(size_t)Cdim * Cdim];         // (WqWp)^T
__device__ __half g_Ab[(size_t)NB * Cdim * Cdim];
__device__ __half g_Mb[(size_t)NB * Cdim * Cdim];
__device__ __half g_wqwqa[(size_t)128 * Cdim];        // rows 0..15 = (WqWqa)^T
__device__ __half g_wkab[(size_t)NB * 128 * Cdim];    // per-batch gated

// ---------------------------------------------------------------------------
// PTX helpers
// ---------------------------------------------------------------------------
__device__ __forceinline__ uint32_t smem_u32(const void* p) {
    uint32_t a;
    asm("{ .reg .u64 t; cvta.to.shared.u64 t, %1; cvt.u32.u64 %0, t; }" : "=r"(a) : "l"(p));
    return a;
}
__device__ __forceinline__ void cpa16(uint32_t dst, const void* src) {
    asm volatile("cp.async.cg.shared.global [%0], [%1], 16;" :: "r"(dst), "l"(src) : "memory");
}
__device__ __forceinline__ void cpa_commit() {
    asm volatile("cp.async.commit_group;" ::: "memory");
}
__device__ __forceinline__ void cpa_wait1() {
    asm volatile("cp.async.wait_group 1;" ::: "memory");
}
__device__ __forceinline__ void ldm_x4(uint32_t* r, uint32_t addr) {
    asm volatile("ldmatrix.sync.aligned.m8n8.x4.shared.b16 {%0,%1,%2,%3}, [%4];"
                 : "=r"(r[0]), "=r"(r[1]), "=r"(r[2]), "=r"(r[3]) : "r"(addr));
}
__device__ __forceinline__ void mma_fp16(float* c, const uint32_t* a, const uint32_t* b) {
    asm volatile(
        "mma.sync.aligned.m16n8k16.row.col.f32.f16.f16.f32 "
        "{%0,%1,%2,%3}, {%4,%5,%6,%7}, {%8,%9}, {%0,%1,%2,%3};"
        : "+f"(c[0]), "+f"(c[1]), "+f"(c[2]), "+f"(c[3])
        : "r"(a[0]), "r"(a[1]), "r"(a[2]), "r"(a[3]), "r"(b[0]), "r"(b[1]));
}

// ---------------------------------------------------------------------------
// HMMA GEMM; slim mode = N=16 logits GEMM
// ---------------------------------------------------------------------------
#define ROWB   144
#define TILEB  (128 * ROWB)
#define STAGEB (2 * TILEB)
#define STAGES 3
#define SMEMB  (STAGES * STAGEB)   // 110592

__device__ __forceinline__ void issue_stage(
    uint32_t sb, int s, int chunk, int tid,
    const __half* Aw, const __half* Bsrc, int grow0, int ncol0, int slim)
{
    uint32_t stb = sb + (uint32_t)s * STAGEB;
    int k0 = chunk * 64;
#pragma unroll
    for (int j = 0; j < 8; j++) {
        int id = tid + j * 256;
        int t4 = id >> 10;
        int w  = id & 1023;
        int r  = w >> 3, c = w & 7;
        if (slim && t4 == 1 && r >= 16) continue;
        const __half* src = (t4 == 0) ? Aw : Bsrc;
        int rb = (t4 == 0) ? grow0 : ncol0;
        const void* g = src + ((size_t)(rb + r) * Cdim + k0 + c * 8);
        cpa16(stb + (uint32_t)t4 * TILEB + (uint32_t)(r * ROWB + c * 16), g);
    }
}

__global__ void __launch_bounds__(256, 2) mma_gemm(
    const __half* __restrict__ Aw, const __half* __restrict__ Bw,
    const __half* __restrict__ Bw2,
    const float* __restrict__ bias, int bias_batched,
    const float* __restrict__ bias2, int bias2_batched,
    const __half* __restrict__ addmat16,
    float* __restrict__ outf, __half* __restrict__ out16,
    float* __restrict__ logits_out,
    size_t bstride, size_t b2stride, int slim)
{
    extern __shared__ char smem[];
    uint32_t sb = smem_u32(smem);
    int tid = threadIdx.x;
    int lane = tid & 31, wid = tid >> 5;
    int wm = wid & 1, wc = wid >> 1;
    int bM = blockIdx.y * 128, bN = blockIdx.x * 128;
    const __half* Bsrc;
    int ncol0;
    if (slim) { Bsrc = Bw2 + (size_t)(bM >> 12) * b2stride; ncol0 = 0; }
    else      { Bsrc = Bw + (size_t)(bM >> 12) * bstride; ncol0 = bN; }

    float acc[4][4][4];
#pragma unroll
    for (int i = 0; i < 4; i++)
#pragma unroll
        for (int j = 0; j < 4; j++)
#pragma unroll
            for (int q = 0; q < 4; q++) acc[i][j][q] = 0.f;

    int grp = lane >> 3, l7 = lane & 7;
    uint32_t a_off = (uint32_t)((l7 + ((grp & 1) << 3)) * ROWB + ((grp >> 1) << 4));
    uint32_t b_off = (uint32_t)((l7 + ((grp >> 1) << 3)) * ROWB + ((grp & 1) << 4));

#pragma unroll
    for (int s = 0; s < 2; s++) {
        issue_stage(sb, s, s, tid, Aw, Bsrc, bM, ncol0, slim);
        cpa_commit();
    }

    for (int k = 0; k < 16; k++) {
        cpa_wait1();
        __syncthreads();
        if (k + 2 < 16)
            issue_stage(sb, (k + 2) % 3, k + 2, tid, Aw, Bsrc, bM, ncol0, slim);
        cpa_commit();

        uint32_t st = sb + (uint32_t)(k % 3) * STAGEB;
        if (!slim) {
#pragma unroll
            for (int kk = 0; kk < 4; kk++) {
                uint32_t kb = (uint32_t)(kk * 32);
                uint32_t bh[8];
#pragma unroll
                for (int h = 0; h < 2; h++) {
                    uint32_t nrow = (uint32_t)((wc * 32 + h * 16) * ROWB);
                    ldm_x4(bh + h * 4, st + TILEB + nrow + b_off + kb);
                }
#pragma unroll
                for (int mt = 0; mt < 4; mt++) {
                    uint32_t mrow = (uint32_t)((wm * 64 + mt * 16) * ROWB);
                    uint32_t ah[4];
                    ldm_x4(ah, st + mrow + a_off + kb);
#pragma unroll
                    for (int nt = 0; nt < 4; nt++)
                        mma_fp16(acc[mt][nt], ah, &bh[nt * 2]);
                }
            }
        } else if (wc == 0) {
#pragma unroll
            for (int kk = 0; kk < 4; kk++) {
                uint32_t kb = (uint32_t)(kk * 32);
                uint32_t bh[4];
                ldm_x4(bh, st + TILEB + b_off + kb);
#pragma unroll
                for (int mt = 0; mt < 4; mt++) {
                    uint32_t mrow = (uint32_t)((wm * 64 + mt * 16) * ROWB);
                    uint32_t ah[4];
                    ldm_x4(ah, st + mrow + a_off + kb);
                    mma_fp16(acc[mt][0], ah, &bh[0]);
                    mma_fp16(acc[mt][1], ah, &bh[2]);
                }
            }
        }
    }

    // ---------------- epilogue ----------------
    int nidx = bM >> 12;
    if (slim) {
        if (wc == 0) {
            const float* b2 = bias2 + (bias2_batched ? (size_t)nidx * Hn : 0);
#pragma unroll
            for (int mt = 0; mt < 4; mt++) {
                int m0 = bM + wm * 64 + mt * 16 + (lane >> 2);
#pragma unroll
                for (int nt = 0; nt < 2; nt++) {
                    int h = nt * 8 + (lane & 3) * 2;
                    float b0 = b2[h], b1 = b2[h + 1];
                    float2 v0 = make_float2((acc[mt][nt][0] + b0) * ATT_SCALE,
                                            (acc[mt][nt][1] + b1) * ATT_SCALE);
                    float2 v1 = make_float2((acc[mt][nt][2] + b0) * ATT_SCALE,
                                            (acc[mt][nt][3] + b1) * ATT_SCALE);
                    *(float2*)(logits_out + (size_t)m0 * Hn + h) = v0;
                    *(float2*)(logits_out + (size_t)(m0 + 8) * Hn + h) = v1;
                }
            }
        }
        return;
    }

    const float* bptr = bias + (bias_batched ? (size_t)nidx * Cdim : 0);
#pragma unroll
    for (int mt = 0; mt < 4; mt++) {
        int m0 = bM + wm * 64 + mt * 16 + (lane >> 2);
#pragma unroll
        for (int nt = 0; nt < 4; nt++) {
            int n = bN + wc * 32 + nt * 8 + (lane & 3) * 2;
            float b0 = bptr[n], b1 = bptr[n + 1];
            float v0 = acc[mt][nt][0] + b0, v1 = acc[mt][nt][1] + b1;
            float v2 = acc[mt][nt][2] + b0, v3 = acc[mt][nt][3] + b1;
            size_t o0 = (size_t)m0 * Cdim + n;
            size_t o1 = (size_t)(m0 + 8) * Cdim + n;
            if (addmat16) {
                float2 a0 = __half22float2(*(const __half2*)(addmat16 + o0));
                float2 a1 = __half22float2(*(const __half2*)(addmat16 + o1));
                v0 += a0.x; v1 += a0.y; v2 += a1.x; v3 += a1.y;
            }
            if (outf) {
                *(float2*)(outf + o0) = make_float2(v0, v1);
                *(float2*)(outf + o1) = make_float2(v2, v3);
            }
            if (out16) {
                *(__half2*)(out16 + o0) =
                    __halves2half2(__float2half(v0), __float2half(v1));
                *(__half2*)(out16 + o1) =
                    __halves2half2(__float2half(v2), __float2half(v3));
            }
        }
    }
}

// ---------------------------------------------------------------------------
// fp32 -> fp16 elementwise
// ---------------------------------------------------------------------------
__global__ __launch_bounds__(256) void cvt_kernel(
    const float* __restrict__ src, __half* __restrict__ dst, int n4)
{
    int i = blockIdx.x * 256 + threadIdx.x;
    if (i >= n4) return;
    float4 x = ((const float4*)src)[i];
    ((__half2*)dst)[2 * i]     = __halves2half2(__float2half(x.x), __float2half(x.y));
    ((__half2*)dst)[2 * i + 1] = __halves2half2(__float2half(x.z), __float2half(x.w));
}

// ---------------------------------------------------------------------------
// W[k][n] fp32 -> WT[n][k] fp16
// ---------------------------------------------------------------------------
__global__ __launch_bounds__(256) void wcvt_kernel(
    const float* __restrict__ W, __half* __restrict__ T16)
{
    __shared__ float t[32][33];
    int tx = threadIdx.x & 31, ty = threadIdx.x >> 5;
    int n0 = blockIdx.x * 32, k0 = blockIdx.y * 32;
#pragma unroll
    for (int i = 0; i < 32; i += 8)
        t[ty + i][tx] = W[(size_t)(k0 + ty + i) * Cdim + n0 + tx];
    __syncthreads();
#pragma unroll
    for (int i = 0; i < 32; i += 8) {
        size_t o = (size_t)(n0 + ty + i) * Cdim + k0 + tx;
        T16[o] = __float2half(t[tx][ty + i]);
    }
}

// ---------------------------------------------------------------------------
// wprod: out[(b*128+h)*C + j] = Σ_c Wleft[j,c]·(scale?scale[b,c]:1)·Wa[c,h]
// ---------------------------------------------------------------------------
__global__ __launch_bounds__(256) void wprod_kernel(
    const float* __restrict__ Wleft, const float* __restrict__ Wa,
    const float* __restrict__ scale, __half* __restrict__ outw)
{
    int gw = blockIdx.x * 8 + (threadIdx.x >> 5);
    int lane = threadIdx.x & 31;
    int b = gw >> 10, j = gw & 1023;
    const float* wl = Wleft + (size_t)j * Cdim;
    const float* sv = scale ? scale + (size_t)b * Cdim : nullptr;

    float acc[16];
#pragma unroll
    for (int h = 0; h < 16; h++) acc[h] = 0.f;
    for (int c = lane; c < Cdim; c += 32) {
        float v = wl[c];
        if (sv) v *= sv[c];
        const float4* a4 = (const float4*)(Wa + (size_t)c * 16);
        float4 a0 = a4[0], a1 = a4[1], a2 = a4[2], a3 = a4[3];
        acc[0]  += v * a0.x; acc[1]  += v * a0.y; acc[2]  += v * a0.z; acc[3]  += v * a0.w;
        acc[4]  += v * a1.x; acc[5]  += v * a1.y; acc[6]  += v * a1.z; acc[7]  += v * a1.w;
        acc[8]  += v * a2.x; acc[9]  += v * a2.y; acc[10] += v * a2.z; acc[11] += v * a2.w;
        acc[12] += v * a3.x; acc[13] += v * a3.y; acc[14] += v * a3.z; acc[15] += v * a3.w;
    }
#pragma unroll
    for (int h = 0; h < 16; h++) {
        float v = acc[h];
#pragma unroll
        for (int o = 16; o; o >>= 1) v += __shfl_xor_sync(0xffffffffu, v, o);
        if (lane == h) outw[((size_t)(b * 128 + h)) * Cdim + j] = __float2half(v);
    }
}

// ---------------------------------------------------------------------------
// blvec
// ---------------------------------------------------------------------------
__global__ __launch_bounds__(512) void blvec_kernel(
    const float* __restrict__ bvec, const float* __restrict__ scale,
    const float* __restrict__ Wa, const float* __restrict__ badd,
    float* __restrict__ outv)
{
    int b = blockIdx.x, h = threadIdx.x >> 5, lane = threadIdx.x & 31;
    float s = 0.f;
    for (int c = lane; c < Cdim; c += 32) {
        float v = bvec[c];
        if (scale) v *= scale[(size_t)b * Cdim + c];
        s += v * Wa[(size_t)c * 16 + h];
    }
#pragma unroll
    for (int o = 16; o; o >>= 1) s += __shfl_xor_sync(0xffffffffu, s, o);
    if (lane == 0) outv[b * 16 + h] = s + badd[h];
}

// ---------------------------------------------------------------------------
// poolx partials (16 L-segments of 256)
// ---------------------------------------------------------------------------
__global__ __launch_bounds__(256) void poolx_kernel(
    const float* __restrict__ w, const __half* __restrict__ x16,
    float* __restrict__ pxp)
{
    int lseg = blockIdx.x, n = blockIdx.y;
    int c = blockIdx.z * 256 + threadIdx.x;
    int tid = threadIdx.x;
    __shared__ float ws[16][128];

    float acc[16];
#pragma unroll
    for (int h = 0; h < 16; h++) acc[h] = 0.f;

    for (int chunk = 0; chunk < 2; chunk++) {
        int lb = lseg * 256 + chunk * 128;
#pragma unroll
        for (int i = 0; i < 8; i++) {
            int idx = tid + i * 256;
            ws[idx >> 7][idx & 127] =
                w[((size_t)n * Hn + (idx >> 7)) * Lseq + lb + (idx & 127)];
        }
        __syncthreads();
        for (int l = 0; l < 128; l++) {
            float a = __half2float(x16[((size_t)(n * Lseq + lb + l)) * Cdim + c]);
#pragma unroll
            for (int h = 0; h < 16; h++) acc[h] = fmaf(ws[h][l], a, acc[h]);
        }
        __syncthreads();
    }
#pragma unroll
    for (int h = 0; h < 16; h++)
        pxp[((size_t)((lseg * 8 + n) * 16 + h)) * Cdim + c] = acc[h];
}

// ---------------------------------------------------------------------------
// pcontract (fused 16-seg reduce)
// ---------------------------------------------------------------------------
__global__ __launch_bounds__(256) void pcontract_kernel(
    const float* __restrict__ pxp, const float* __restrict__ Wx,
    const float* __restrict__ bvec, float* __restrict__ pooled)
{
    int h = blockIdx.x, n = blockIdx.y;
    int tid = threadIdx.x;
    int d = tid & 63, seg = tid >> 6;
    int hn = n * Hn + h;
    __shared__ float ps[Cdim];
    for (int j = tid; j < Cdim; j += 256) {
        float s = 0.f;
#pragma unroll
        for (int ls = 0; ls < 16; ls++)
            s += pxp[((size_t)(ls * 128 + hn)) * Cdim + j];
        ps[j] = s;
    }
    __syncthreads();
    float acc = 0.f;
    for (int j = seg * 256; j < seg * 256 + 256; j++)
        acc = fmaf(ps[j], Wx[(size_t)j * Cdim + h * 64 + d], acc);
    __shared__ float red[256];
    red[tid] = acc;
    __syncthreads();
    if (tid < 64) {
        float s = red[tid] + red[tid + 64] + red[tid + 128] + red[tid + 192];
        pooled[(size_t)n * Cdim + h * 64 + tid] = s + bvec[h * 64 + tid];
    }
}

// ---------------------------------------------------------------------------
// softmax over L
// ---------------------------------------------------------------------------
__global__ __launch_bounds__(256) void softmax_L_kernel(
    const float* __restrict__ logits, float* __restrict__ w_out)
{
    int n = blockIdx.x / Hn, h = blockIdx.x % Hn;
    __shared__ float buf[Lseq];
    __shared__ float red[256];
    int tid = threadIdx.x;

    float m = -1e30f;
    for (int l = tid; l < Lseq; l += 256) {
        float v = logits[((size_t)n * Lseq + l) * Hn + h];
        buf[l] = v;
        m = fmaxf(m, v);
    }
    red[tid] = m; __syncthreads();
    for (int s = 128; s; s >>= 1) {
        if (tid < s) red[tid] = fmaxf(red[tid], red[tid + s]);
        __syncthreads();
    }
    m = red[0]; __syncthreads();

    float sum = 0.f;
    for (int l = tid; l < Lseq; l += 256) {
        float e = __expf(buf[l] - m);
        buf[l] = e;
        sum += e;
    }
    red[tid] = sum; __syncthreads();
    for (int s = 128; s; s >>= 1) {
        if (tid < s) red[tid] += red[tid + s];
        __syncthreads();
    }
    float inv = 1.f / red[0];

    float* wp = w_out + ((size_t)n * Hn + h) * Lseq;
    for (int l = tid; l < Lseq; l += 256) wp[l] = buf[l] * inv;
}

// ---------------------------------------------------------------------------
// wtb / cb
// ---------------------------------------------------------------------------
__global__ __launch_bounds__(256) void wtb_kernel(
    const float* __restrict__ pk, const __half* __restrict__ src,
    __half* __restrict__ outw)
{
    size_t i = (size_t)blockIdx.x * 256 + threadIdx.x;
    int k2 = (int)(i & 511);
    int n  = (int)((i >> 9) & 1023);
    int b  = (int)(i >> 19);
    float2 wf = __half22float2(((const __half2*)src)[((size_t)n << 9) | k2]);
    float s0 = pk[b * Cdim + k2 * 2];
    float s1 = pk[b * Cdim + k2 * 2 + 1];
    ((__half2*)outw)[i] = __floats2half2_rn(wf.x * s0, wf.y * s1);
}

__global__ __launch_bounds__(256) void cb_kernel(
    const float* __restrict__ pk, const __half* __restrict__ wtwp,
    const __half* __restrict__ wp16,
    const float* __restrict__ bv, const float* __restrict__ bt,
    const float* __restrict__ bq, const float* __restrict__ bp,
    float* __restrict__ cb)
{
    int warp = threadIdx.x >> 5, lane = threadIdx.x & 31;
    int idx = blockIdx.x * 8 + warp;
    int b = idx >> 10, n = idx & 1023;
    float s = 0.f;
    for (int j = lane; j < Cdim; j += 32) {
        s += __half2float(wtwp[(size_t)n * Cdim + j]) * bv[j] * pk[b * Cdim + j];
        s += __half2float(wp16[(size_t)n * Cdim + j]) * (bt[j] + bq[j]);
    }
#pragma unroll
    for (int o = 16; o; o >>= 1) s += __shfl_xor_sync(0xffffffffu, s, o);
    if (lane == 0) cb[b * Cdim + n] = s + bp[n];
}

// ---------------------------------------------------------------------------
// Launch — every cudaStreamWaitEvent strictly AFTER its cudaEventRecord
// in host order (capture-valid DAG edges).
// ---------------------------------------------------------------------------
extern "C" void kernel_launch(void* const* d_in, const int* in_sizes, int n_in,
                              void* d_out, int out_size)
{
    const float* x_q  = (const float*)d_in[0];
    const float* x_kv = (const float*)d_in[1];
    const float* Wq   = (const float*)d_in[2];
    const float* bq   = (const float*)d_in[3];
    const float* Wqa  = (const float*)d_in[4];
    const float* bqa  = (const float*)d_in[5];
    const float* Wk   = (const float*)d_in[6];
    const float* bk   = (const float*)d_in[7];
    const float* Wka  = (const float*)d_in[8];
    const float* bka  = (const float*)d_in[9];
    const float* Wv   = (const float*)d_in[10];
    const float* bv   = (const float*)d_in[11];
    const float* Wt   = (const float*)d_in[12];
    const float* bt   = (const float*)d_in[13];
    const float* Wp   = (const float*)d_in[14];
    const float* bp   = (const float*)d_in[15];
    float* out = (float*)d_out;

    float *lg, *wb, *pq, *pk, *cbv, *zeros, *pxp, *blq, *blk;
    __half *xq16, *xkv16, *P16, *wp16, *wqrm, *wtrm, *wvrm, *wtwp, *g16;
    __half *Ab, *Mb, *wqwqa, *wkab;
    cudaGetSymbolAddress((void**)&lg, g_logits);
    cudaGetSymbolAddress((void**)&wb, g_wbuf);
    cudaGetSymbolAddress((void**)&pq, g_pq);
    cudaGetSymbolAddress((void**)&pk, g_pk);
    cudaGetSymbolAddress((void**)&cbv, g_cb);
    cudaGetSymbolAddress((void**)&zeros, g_zeros);
    cudaGetSymbolAddress((void**)&pxp, g_pxp);
    cudaGetSymbolAddress((void**)&blq, g_blq);
    cudaGetSymbolAddress((void**)&blk, g_blk);
    cudaGetSymbolAddress((void**)&xq16, g_xq16);
    cudaGetSymbolAddress((void**)&xkv16, g_xkv16);
    cudaGetSymbolAddress((void**)&P16, g_P16);
    cudaGetSymbolAddress((void**)&wp16, g_wp16);
    cudaGetSymbolAddress((void**)&wqrm, g_wqrm);
    cudaGetSymbolAddress((void**)&wtrm, g_wtrm);
    cudaGetSymbolAddress((void**)&wvrm, g_wvrm);
    cudaGetSymbolAddress((void**)&wtwp, g_wtwp);
    cudaGetSymbolAddress((void**)&g16, g_g16);
    cudaGetSymbolAddress((void**)&Ab, g_Ab);
    cudaGetSymbolAddress((void**)&Mb, g_Mb);
    cudaGetSymbolAddress((void**)&wqwqa, g_wqwqa);
    cudaGetSymbolAddress((void**)&wkab, g_wkab);

    const size_t WSZ = (size_t)Cdim * Cdim;
    const size_t HALF_M = (size_t)(Mrows / 2) * Cdim;     // 16384 rows
    const size_t HALF_W = (size_t)4 * WSZ;                // 4 batches of weights
    cudaFuncSetAttribute(mma_gemm, cudaFuncAttributeMaxDynamicSharedMemorySize, SMEMB);

    cudaStream_t s1;
    cudaStreamCreateWithFlags(&s1, cudaStreamNonBlocking);
    cudaEvent_t evFork, evWq, evCvtXq, evCvtKv, evWtwp, evPk, evCb;
    cudaEvent_t evP10, evP11, evMb1;
    cudaEventCreateWithFlags(&evFork,  cudaEventDisableTiming);
    cudaEventCreateWithFlags(&evWq,    cudaEventDisableTiming);
    cudaEventCreateWithFlags(&evCvtXq, cudaEventDisableTiming);
    cudaEventCreateWithFlags(&evCvtKv, cudaEventDisableTiming);
    cudaEventCreateWithFlags(&evWtwp,  cudaEventDisableTiming);
    cudaEventCreateWithFlags(&evPk,    cudaEventDisableTiming);
    cudaEventCreateWithFlags(&evCb,    cudaEventDisableTiming);
    cudaEventCreateWithFlags(&evP10,   cudaEventDisableTiming);
    cudaEventCreateWithFlags(&evP11,   cudaEventDisableTiming);
    cudaEventCreateWithFlags(&evMb1,   cudaEventDisableTiming);

    int n4 = Mrows * Cdim / 4;
    int w4 = Cdim * Cdim / 4;
    dim3 wg(32, 32);
    dim3 ggh(8, Mrows / 256);    // half-M big GEMM (128 y-tiles)
    dim3 ggs(1, Mrows / 128);
    dim3 ggw(8, 8);
    dim3 ggmh(8, 32);            // half Mb GEMM
    dim3 ggpool(16, 8, 4);

    // ---- fork ----
    cudaEventRecord(evFork, 0);
    cudaStreamWaitEvent(s1, evFork, 0);

    // s1 prologue: q logit weights, kv convert, weight chain
    wprod_kernel<<<128, 256, 0, s1>>>(Wq, Wqa, nullptr, wqwqa);
    blvec_kernel<<<1, 512, 0, s1>>>(bq, nullptr, Wqa, bqa, blq);
    cudaEventRecord(evWq, s1);
    cvt_kernel<<<(n4 + 255) / 256, 256, 0, s1>>>(x_kv, xkv16, n4);
    cudaEventRecord(evCvtKv, s1);
    wcvt_kernel<<<wg, 256, 0, s1>>>(Wp, wp16);
    cvt_kernel<<<(w4 + 255) / 256, 256, 0, s1>>>(Wt, wtrm, w4);
    cvt_kernel<<<(w4 + 255) / 256, 256, 0, s1>>>(Wq, wqrm, w4);
    cvt_kernel<<<(w4 + 255) / 256, 256, 0, s1>>>(Wv, wvrm, w4);
    mma_gemm<<<ggw, 256, SMEMB, s1>>>(wp16, wtrm, nullptr, zeros, 0, nullptr, 0,
                                      nullptr, nullptr, wtwp, nullptr, 0, 0, 0);
    cudaEventRecord(evWtwp, s1);
    mma_gemm<<<ggw, 256, SMEMB, s1>>>(wp16, wqrm, nullptr, zeros, 0, nullptr, 0,
                                      nullptr, nullptr, g16, nullptr, 0, 0, 0);

    // main: cvt_xq (record BEFORE s1's P1 wait is enqueued)
    cvt_kernel<<<(n4 + 255) / 256, 256>>>(x_q, xq16, n4);
    cudaEventRecord(evCvtXq, 0);

    // s1: P1 halves (wait now has a valid edge)
    cudaStreamWaitEvent(s1, evCvtXq, 0);
    mma_gemm<<<ggh, 256, SMEMB, s1>>>(xq16, g16, nullptr, zeros, 0, nullptr, 0,
                                      nullptr, nullptr, P16, nullptr, 0, 0, 0);
    cudaEventRecord(evP10, s1);
    mma_gemm<<<ggh, 256, SMEMB, s1>>>(xq16 + HALF_M, g16, nullptr, zeros, 0,
                                      nullptr, 0, nullptr, nullptr,
                                      P16 + HALF_M, nullptr, 0, 0, 0);
    cudaEventRecord(evP11, s1);

    // main: q chain
    cudaStreamWaitEvent(0, evWq, 0);
    mma_gemm<<<ggs, 256, SMEMB>>>(xq16, nullptr, wqwqa, nullptr, 0, blq, 0,
                                  nullptr, nullptr, nullptr, lg, 0, 0, 1);
    softmax_L_kernel<<<NB * Hn, 256>>>(lg, wb);
    poolx_kernel<<<ggpool, 256>>>(wb, xq16, pxp);
    pcontract_kernel<<<dim3(Hn, NB), 256>>>(pxp, Wq, bq, pq);

    // main: k chain (gated by pq)
    wprod_kernel<<<1024, 256>>>(Wk, Wka, pq, wkab);
    blvec_kernel<<<NB, 512>>>(bk, pq, Wka, bka, blk);
    cudaStreamWaitEvent(0, evCvtKv, 0);
    mma_gemm<<<ggs, 256, SMEMB>>>(xkv16, nullptr, wkab, nullptr, 0, blk, 1,
                                  nullptr, nullptr, nullptr, lg, 0,
                                  (size_t)128 * Cdim, 1);
    softmax_L_kernel<<<NB * Hn, 256>>>(lg, wb);
    poolx_kernel<<<ggpool, 256>>>(wb, xkv16, pxp);
    pcontract_kernel<<<dim3(Hn, NB), 256>>>(pxp, Wk, bk, pk);
    cudaEventRecord(evPk, 0);

    // s1 tail (enqueued AFTER evPk record -> valid edge):
    // cb + second-half wtb/Mb, parallel with main's half0 + P2 half0
    cudaStreamWaitEvent(s1, evPk, 0);
    cb_kernel<<<(NB * Cdim) / 8, 256, 0, s1>>>(pk, wtwp, wp16, bv, bt, bq, bp, cbv);
    cudaEventRecord(evCb, s1);
    wtb_kernel<<<(4 * Cdim * (Cdim / 2)) / 256, 256, 0, s1>>>(
        pk + 4 * Cdim, wtwp, Ab + HALF_W);
    mma_gemm<<<ggmh, 256, SMEMB, s1>>>(Ab + HALF_W, wvrm, nullptr, zeros, 0,
                                       nullptr, 0, nullptr, nullptr,
                                       Mb + HALF_W, nullptr, 0, 0, 0);
    cudaEventRecord(evMb1, s1);

    // main: first-half wtb/Mb, then pipelined P2 halves
    cudaStreamWaitEvent(0, evWtwp, 0);
    wtb_kernel<<<(4 * Cdim * (Cdim / 2)) / 256, 256>>>(pk, wtwp, Ab);
    mma_gemm<<<ggmh, 256, SMEMB>>>(Ab, wvrm, nullptr, zeros, 0, nullptr, 0,
                                   nullptr, nullptr, Mb, nullptr, 0, 0, 0);
    cudaStreamWaitEvent(0, evP10, 0);
    cudaStreamWaitEvent(0, evCb, 0);
    mma_gemm<<<ggh, 256, SMEMB>>>(xkv16, Mb, nullptr, cbv, 1, nullptr, 0,
                                  P16, out, nullptr, nullptr, WSZ, 0, 0);
    cudaStreamWaitEvent(0, evP11, 0);
    cudaStreamWaitEvent(0, evMb1, 0);
    mma_gemm<<<ggh, 256, SMEMB>>>(xkv16 + HALF_M, Mb + HALF_W, nullptr,
                                  cbv + 4 * Cdim, 1, nullptr, 0,
                                  P16 + HALF_M, out + HALF_M, nullptr, nullptr,
                                  WSZ, 0, 0);
}